// round 1
// baseline (speedup 1.0000x reference)
#include <cuda_runtime.h>

#define Bq   8
#define Sq   1024
#define HIDq 1024
#define NHq  16
#define HDq  64
#define Mq   (Bq * Sq)   // 8192

// Scratch (device globals: allocation-free per harness rules)
__device__ float g_q[(size_t)Bq * NHq * Sq * HDq];    // [B,NH,S,HD]
__device__ float g_k[(size_t)Bq * NHq * Sq * HDq];
__device__ float g_v[(size_t)Bq * NHq * Sq * HDq];
__device__ float g_ctx[(size_t)Mq * HIDq];            // [B,S,HID]

// ---------------------------------------------------------------------------
// SGEMM: C = A[8192,1024] @ W[1024,1024] + bias
// MODE 0/1/2: A = Ain (x), C = g_q/g_k/g_v scattered into [B,NH,S,HD]
// MODE 3    : A = g_ctx,   C = Cout (d_out) plain row-major
// BM=BN=128, BK=8, 256 threads, 8x8 per thread.
// ---------------------------------------------------------------------------
template <int MODE>
__global__ __launch_bounds__(256) void sgemm_kernel(
    const float* __restrict__ Ain, const float* __restrict__ W,
    const float* __restrict__ bias, float* __restrict__ Cout)
{
    const int K = HIDq, N = HIDq;
    const float* A = (MODE == 3) ? g_ctx : Ain;
    float* C = (MODE == 0) ? g_q : (MODE == 1) ? g_k : (MODE == 2) ? g_v : Cout;

    __shared__ float As[8][128];
    __shared__ float Bs[8][128];

    const int tid = threadIdx.x;
    const int tx = tid & 15, ty = tid >> 4;
    const int bm = blockIdx.y * 128, bn = blockIdx.x * 128;

    const int arow = tid >> 1;          // 0..127
    const int acol = (tid & 1) * 4;     // 0 or 4
    const int brow = tid >> 5;          // 0..7
    const int bcol = (tid & 31) * 4;    // 0..124

    float acc[8][8];
#pragma unroll
    for (int i = 0; i < 8; i++)
#pragma unroll
        for (int j = 0; j < 8; j++) acc[i][j] = 0.f;

    for (int k0 = 0; k0 < K; k0 += 8) {
        float4 av = *(const float4*)(A + (size_t)(bm + arow) * K + k0 + acol);
        As[acol + 0][arow] = av.x;
        As[acol + 1][arow] = av.y;
        As[acol + 2][arow] = av.z;
        As[acol + 3][arow] = av.w;
        *(float4*)(&Bs[brow][bcol]) =
            *(const float4*)(W + (size_t)(k0 + brow) * N + bn + bcol);
        __syncthreads();

#pragma unroll
        for (int kk = 0; kk < 8; kk++) {
            float rm[8], rn[8];
            *(float4*)(rm)     = *(const float4*)(&As[kk][ty * 8]);
            *(float4*)(rm + 4) = *(const float4*)(&As[kk][ty * 8 + 4]);
            *(float4*)(rn)     = *(const float4*)(&Bs[kk][tx * 8]);
            *(float4*)(rn + 4) = *(const float4*)(&Bs[kk][tx * 8 + 4]);
#pragma unroll
            for (int i = 0; i < 8; i++)
#pragma unroll
                for (int j = 0; j < 8; j++)
                    acc[i][j] = fmaf(rm[i], rn[j], acc[i][j]);
        }
        __syncthreads();
    }

#pragma unroll
    for (int i = 0; i < 8; i++) {
        const int row = bm + ty * 8 + i;
#pragma unroll
        for (int j = 0; j < 8; j++) {
            const int col = bn + tx * 8 + j;
            const float v = acc[i][j] + bias[col];
            if (MODE == 3) {
                C[(size_t)row * N + col] = v;
            } else {
                const int b = row >> 10, s = row & 1023;
                const int h = col >> 6,  d = col & 63;
                C[(((size_t)(b * NHq + h)) * Sq + s) * HDq + d] = v;
            }
        }
    }
}

// ---------------------------------------------------------------------------
// Flash-style attention over one (b,h) with 64-row query tiles.
// Block: 256 threads (16x16), each thread owns a 4x4 score/output subtile.
// Streams 64-key tiles: S = Q K^T * (1/32) + mask*(-1e9), online softmax,
// O += P @ V. ctx written directly in [B,S,HID] layout.
// ---------------------------------------------------------------------------
__global__ __launch_bounds__(256) void attn_kernel(const float* __restrict__ mask)
{
    extern __shared__ float smdyn[];
    float* Qs  = smdyn;                 // 64*65
    float* KVs = smdyn + 64 * 65;       // 64*65 (K, then reused for V)
    float* Ps  = smdyn + 2 * 64 * 65;   // 64*65

    const int bh = blockIdx.y;          // b*NH + h
    const int b = bh >> 4, h = bh & 15;
    const int qbase = blockIdx.x * 64;
    const int tid = threadIdx.x;
    const int tx = tid & 15, ty = tid >> 4;

    const float* Q  = g_q + (size_t)bh * Sq * HDq;
    const float* Kp = g_k + (size_t)bh * Sq * HDq;
    const float* Vp = g_v + (size_t)bh * Sq * HDq;

    // Load Q tile [64,64]
    for (int i = tid; i < 1024; i += 256) {
        const int r = i >> 4, c = (i & 15) << 2;
        float4 v = *(const float4*)(Q + (size_t)(qbase + r) * HDq + c);
        Qs[r * 65 + c + 0] = v.x; Qs[r * 65 + c + 1] = v.y;
        Qs[r * 65 + c + 2] = v.z; Qs[r * 65 + c + 3] = v.w;
    }

    float m_r[4], l_r[4], o[4][4];
#pragma unroll
    for (int i = 0; i < 4; i++) {
        m_r[i] = -1e30f; l_r[i] = 0.f;
#pragma unroll
        for (int j = 0; j < 4; j++) o[i][j] = 0.f;
    }
    __syncthreads();

    const float scale = 0.03125f;  // rsqrt(1024)

    for (int kt = 0; kt < Sq / 64; kt++) {
        const int kbase = kt * 64;

        // Load K tile
        for (int i = tid; i < 1024; i += 256) {
            const int r = i >> 4, c = (i & 15) << 2;
            float4 v = *(const float4*)(Kp + (size_t)(kbase + r) * HDq + c);
            KVs[r * 65 + c + 0] = v.x; KVs[r * 65 + c + 1] = v.y;
            KVs[r * 65 + c + 2] = v.z; KVs[r * 65 + c + 3] = v.w;
        }
        __syncthreads();

        // S = Q K^T
        float s[4][4];
#pragma unroll
        for (int i = 0; i < 4; i++)
#pragma unroll
            for (int j = 0; j < 4; j++) s[i][j] = 0.f;

#pragma unroll 8
        for (int d = 0; d < 64; d++) {
            float qv[4], kv[4];
#pragma unroll
            for (int i = 0; i < 4; i++) qv[i] = Qs[(ty * 4 + i) * 65 + d];
#pragma unroll
            for (int j = 0; j < 4; j++) kv[j] = KVs[(tx * 4 + j) * 65 + d];
#pragma unroll
            for (int i = 0; i < 4; i++)
#pragma unroll
                for (int j = 0; j < 4; j++)
                    s[i][j] = fmaf(qv[i], kv[j], s[i][j]);
        }

        // scale + mask
        const float* mp = mask + ((size_t)b * Sq + qbase + ty * 4) * Sq + kbase + tx * 4;
#pragma unroll
        for (int i = 0; i < 4; i++) {
            float4 mv = *(const float4*)(mp + (size_t)i * Sq);
            s[i][0] = fmaf(mv.x, -1e9f, s[i][0] * scale);
            s[i][1] = fmaf(mv.y, -1e9f, s[i][1] * scale);
            s[i][2] = fmaf(mv.z, -1e9f, s[i][2] * scale);
            s[i][3] = fmaf(mv.w, -1e9f, s[i][3] * scale);
        }

        // online softmax (row reductions across 16-lane groups)
#pragma unroll
        for (int i = 0; i < 4; i++) {
            float mx = fmaxf(fmaxf(s[i][0], s[i][1]), fmaxf(s[i][2], s[i][3]));
            mx = fmaxf(mx, __shfl_xor_sync(0xffffffffu, mx, 1, 16));
            mx = fmaxf(mx, __shfl_xor_sync(0xffffffffu, mx, 2, 16));
            mx = fmaxf(mx, __shfl_xor_sync(0xffffffffu, mx, 4, 16));
            mx = fmaxf(mx, __shfl_xor_sync(0xffffffffu, mx, 8, 16));
            const float mnew  = fmaxf(m_r[i], mx);
            const float alpha = __expf(m_r[i] - mnew);
            float psum = 0.f;
#pragma unroll
            for (int j = 0; j < 4; j++) {
                const float p = __expf(s[i][j] - mnew);
                Ps[(ty * 4 + i) * 65 + tx * 4 + j] = p;
                psum += p;
            }
            psum += __shfl_xor_sync(0xffffffffu, psum, 1, 16);
            psum += __shfl_xor_sync(0xffffffffu, psum, 2, 16);
            psum += __shfl_xor_sync(0xffffffffu, psum, 4, 16);
            psum += __shfl_xor_sync(0xffffffffu, psum, 8, 16);
            l_r[i] = l_r[i] * alpha + psum;
            m_r[i] = mnew;
#pragma unroll
            for (int j = 0; j < 4; j++) o[i][j] *= alpha;
        }
        __syncthreads();  // Ps written; KVs (K) no longer needed

        // Load V tile into KVs
        for (int i = tid; i < 1024; i += 256) {
            const int r = i >> 4, c = (i & 15) << 2;
            float4 v = *(const float4*)(Vp + (size_t)(kbase + r) * HDq + c);
            KVs[r * 65 + c + 0] = v.x; KVs[r * 65 + c + 1] = v.y;
            KVs[r * 65 + c + 2] = v.z; KVs[r * 65 + c + 3] = v.w;
        }
        __syncthreads();

        // O += P @ V
#pragma unroll 8
        for (int k = 0; k < 64; k++) {
            float pv[4], vv[4];
#pragma unroll
            for (int i = 0; i < 4; i++) pv[i] = Ps[(ty * 4 + i) * 65 + k];
#pragma unroll
            for (int j = 0; j < 4; j++) vv[j] = KVs[k * 65 + tx * 4 + j];
#pragma unroll
            for (int i = 0; i < 4; i++)
#pragma unroll
                for (int j = 0; j < 4; j++)
                    o[i][j] = fmaf(pv[i], vv[j], o[i][j]);
        }
        __syncthreads();
    }

    // normalize and write ctx in [B,S,HID] layout
#pragma unroll
    for (int i = 0; i < 4; i++) {
        const float inv = 1.0f / l_r[i];
        float4 ov = make_float4(o[i][0] * inv, o[i][1] * inv,
                                o[i][2] * inv, o[i][3] * inv);
        *(float4*)(g_ctx + ((size_t)(b * Sq + qbase + ty * 4 + i)) * HIDq
                   + h * HDq + tx * 4) = ov;
    }
}

// ---------------------------------------------------------------------------
extern "C" void kernel_launch(void* const* d_in, const int* in_sizes, int n_in,
                              void* d_out, int out_size)
{
    (void)in_sizes; (void)n_in; (void)out_size;
    const float* x   = (const float*)d_in[0];
    const float* msk = (const float*)d_in[1];
    const float* Wq  = (const float*)d_in[2];
    const float* bq  = (const float*)d_in[3];
    const float* Wk  = (const float*)d_in[4];
    const float* bk  = (const float*)d_in[5];
    const float* Wv  = (const float*)d_in[6];
    const float* bv  = (const float*)d_in[7];
    const float* Wp  = (const float*)d_in[8];
    const float* bp  = (const float*)d_in[9];
    float* out = (float*)d_out;

    const dim3 gg(HIDq / 128, Mq / 128);  // 8 x 64 blocks
    sgemm_kernel<0><<<gg, 256>>>(x, Wq, bq, nullptr);
    sgemm_kernel<1><<<gg, 256>>>(x, Wk, bk, nullptr);
    sgemm_kernel<2><<<gg, 256>>>(x, Wv, bv, nullptr);

    const int smem = 3 * 64 * 65 * (int)sizeof(float);  // 49920 B
    cudaFuncSetAttribute(attn_kernel, cudaFuncAttributeMaxDynamicSharedMemorySize, smem);
    attn_kernel<<<dim3(Sq / 64, Bq * NHq), 256, smem>>>(msk);

    sgemm_kernel<3><<<gg, 256>>>(nullptr, Wp, bp, out);
}

// round 3
// speedup vs baseline: 1.6922x; 1.6922x over previous
#include <cuda_runtime.h>
#include <cuda_bf16.h>
#include <cstdint>

#define Bq   8
#define Sq   1024
#define HIDq 1024
#define NHq  16
#define HDq  64
#define Mq   (Bq * Sq)   // 8192

// Scratch (device globals: allocation-free per harness rules)
__device__ float g_q[(size_t)Bq * NHq * Sq * HDq];    // [B,NH,S,HD]
__device__ float g_k[(size_t)Bq * NHq * Sq * HDq];
__device__ float g_v[(size_t)Bq * NHq * Sq * HDq];
__device__ float g_ctx[(size_t)Mq * HIDq];            // [B,S,HID]
__device__ __nv_bfloat16 g_xhi[(size_t)Mq * HIDq];    // A operand hi  [M,K]
__device__ __nv_bfloat16 g_xlo[(size_t)Mq * HIDq];    // A operand lo
__device__ __nv_bfloat16 g_wthi[(size_t)HIDq * HIDq]; // W^T hi [N,K]
__device__ __nv_bfloat16 g_wtlo[(size_t)HIDq * HIDq]; // W^T lo

// ===========================================================================
// PTX helpers (portable tensor ISA: ldmatrix + mma.sync, sm_80+)
// ===========================================================================
__device__ __forceinline__ uint32_t smem_to_u32(const void* p) {
    uint32_t a;
    asm("{ .reg .u64 t; cvta.to.shared.u64 t, %1; cvt.u32.u64 %0, t; }"
        : "=r"(a) : "l"(p));
    return a;
}

#define LDMX4(r, addr) \
    asm volatile("ldmatrix.sync.aligned.m8n8.x4.shared.b16 {%0,%1,%2,%3}, [%4];" \
        : "=r"((r)[0]), "=r"((r)[1]), "=r"((r)[2]), "=r"((r)[3]) : "r"(addr))

#define LDMX2(r, addr) \
    asm volatile("ldmatrix.sync.aligned.m8n8.x2.shared.b16 {%0,%1}, [%2];" \
        : "=r"((r)[0]), "=r"((r)[1]) : "r"(addr))

#define MMA_BF16(d, a, b) \
    asm volatile("mma.sync.aligned.m16n8k16.row.col.f32.bf16.bf16.f32 " \
        "{%0,%1,%2,%3}, {%4,%5,%6,%7}, {%8,%9}, {%0,%1,%2,%3};" \
        : "+f"((d)[0]), "+f"((d)[1]), "+f"((d)[2]), "+f"((d)[3]) \
        : "r"((a)[0]), "r"((a)[1]), "r"((a)[2]), "r"((a)[3]), \
          "r"((b)[0]), "r"((b)[1]))

#define CP_ASYNC16(smem, gmem) \
    asm volatile("cp.async.cg.shared.global [%0], [%1], 16;" \
        :: "r"(smem), "l"(gmem) : "memory")
#define CP_COMMIT()  asm volatile("cp.async.commit_group;" ::: "memory")
#define CP_WAIT(n)   asm volatile("cp.async.wait_group %0;" :: "n"(n) : "memory")

// ===========================================================================
// Conversion: fp32 -> bf16 hi/lo split (x or ctx -> g_xhi/g_xlo)
// ===========================================================================
template <bool FROM_CTX>
__global__ __launch_bounds__(256) void convert_x_kernel(const float* __restrict__ src_in)
{
    const float* src = FROM_CTX ? (const float*)g_ctx : src_in;
    const size_t i = ((size_t)blockIdx.x * 256 + threadIdx.x) * 8;
    float4 v0 = *(const float4*)(src + i);
    float4 v1 = *(const float4*)(src + i + 4);
    float f[8] = {v0.x, v0.y, v0.z, v0.w, v1.x, v1.y, v1.z, v1.w};

    uint32_t hw[4], lw[4];
#pragma unroll
    for (int j = 0; j < 4; j++) {
        float a = f[2 * j], b = f[2 * j + 1];
        __nv_bfloat16 ha = __float2bfloat16(a), hb = __float2bfloat16(b);
        __nv_bfloat16 la = __float2bfloat16(a - __bfloat162float(ha));
        __nv_bfloat16 lb = __float2bfloat16(b - __bfloat162float(hb));
        __nv_bfloat162 h2 = __nv_bfloat162(ha, hb);
        __nv_bfloat162 l2 = __nv_bfloat162(la, lb);
        hw[j] = *(uint32_t*)&h2;
        lw[j] = *(uint32_t*)&l2;
    }
    *(uint4*)(g_xhi + i) = make_uint4(hw[0], hw[1], hw[2], hw[3]);
    *(uint4*)(g_xlo + i) = make_uint4(lw[0], lw[1], lw[2], lw[3]);
}

// ===========================================================================
// Weight transpose + split: g_wt{hi,lo}[n][k] = split(W[k][n])
// ===========================================================================
__global__ __launch_bounds__(256) void convw_kernel(const float* __restrict__ W)
{
    __shared__ float tile[32][33];
    const int bx = blockIdx.x * 32, by = blockIdx.y * 32;
    const int tx = threadIdx.x & 31, ty = threadIdx.x >> 5;  // 32 x 8
#pragma unroll
    for (int i = 0; i < 4; i++)
        tile[ty + i * 8][tx] = W[(size_t)(by + ty + i * 8) * HIDq + bx + tx];
    __syncthreads();
#pragma unroll
    for (int i = 0; i < 4; i++) {
        const float v = tile[tx][ty + i * 8];
        const __nv_bfloat16 h = __float2bfloat16(v);
        const size_t o = (size_t)(bx + ty + i * 8) * HIDq + by + tx;
        g_wthi[o] = h;
        g_wtlo[o] = __float2bfloat16(v - __bfloat162float(h));
    }
}

// ===========================================================================
// 3x-bf16 mma.sync GEMM: C = A[8192,1024] @ W[1024,1024] + bias
// A = (g_xhi,g_xlo), B = (g_wthi,g_wtlo) [N,K].
// CTA 128x128, 8 warps (2m x 4n), warp tile 64x32, K-chunk 32, double buffer.
// MODE 0/1/2: scatter to g_q/g_k/g_v [B,NH,S,HD]; MODE 3: row-major to d_out.
// ===========================================================================
#define KCH     32
#define ASTR    40                      // padded row: 40 bf16 = 80 B (16B-aligned, conflict-free)
#define TILEB   (128 * ASTR * 2)        // 10240 B per tile
#define GSMEM   (8 * TILEB)             // 81920 B (2 bufs x {Ahi,Alo,Bhi,Blo})

template <int MODE>
__global__ __launch_bounds__(256, 2) void gemm_mma_kernel(
    const float* __restrict__ bias, float* __restrict__ Cout)
{
    extern __shared__ char sm[];
    const uint32_t sb = smem_to_u32(sm);
    float* C = (MODE == 0) ? g_q : (MODE == 1) ? g_k : (MODE == 2) ? g_v : Cout;

    const int tid = threadIdx.x, lane = tid & 31, wid = tid >> 5;
    const int wm = wid >> 2, wn = wid & 3;             // 2 x 4 warp grid
    const int bm = blockIdx.y * 128, bn = blockIdx.x * 128;

    float acc[4][4][4];
#pragma unroll
    for (int mi = 0; mi < 4; mi++)
#pragma unroll
        for (int ni = 0; ni < 4; ni++)
#pragma unroll
            for (int r = 0; r < 4; r++) acc[mi][ni][r] = 0.f;

    // per-thread cp.async geometry: 512 x 16B segs per tile, 2 per thread
    const int g0 = tid, g1 = tid + 256;
    const int r0g = g0 >> 2, s0 = g0 & 3;
    const int r1g = g1 >> 2, s1 = g1 & 3;

    auto issue = [&](int c) {
        const int p = c & 1;
        const uint32_t base = sb + (uint32_t)p * 4 * TILEB;
        const int k0 = c * KCH;
        const uint32_t so0 = (uint32_t)r0g * 80 + (uint32_t)s0 * 16;
        const uint32_t so1 = (uint32_t)r1g * 80 + (uint32_t)s1 * 16;
        const size_t ga0 = (size_t)(bm + r0g) * HIDq + k0 + s0 * 8;
        const size_t ga1 = (size_t)(bm + r1g) * HIDq + k0 + s1 * 8;
        const size_t gb0 = (size_t)(bn + r0g) * HIDq + k0 + s0 * 8;
        const size_t gb1 = (size_t)(bn + r1g) * HIDq + k0 + s1 * 8;
        CP_ASYNC16(base + so0,             g_xhi  + ga0);
        CP_ASYNC16(base + so1,             g_xhi  + ga1);
        CP_ASYNC16(base + TILEB + so0,     g_xlo  + ga0);
        CP_ASYNC16(base + TILEB + so1,     g_xlo  + ga1);
        CP_ASYNC16(base + 2 * TILEB + so0, g_wthi + gb0);
        CP_ASYNC16(base + 2 * TILEB + so1, g_wthi + gb1);
        CP_ASYNC16(base + 3 * TILEB + so0, g_wtlo + gb0);
        CP_ASYNC16(base + 3 * TILEB + so1, g_wtlo + gb1);
        CP_COMMIT();
    };

    issue(0);

    for (int c = 0; c < HIDq / KCH; c++) {
        if (c + 1 < HIDq / KCH) { issue(c + 1); CP_WAIT(1); }
        else                    { CP_WAIT(0); }
        __syncthreads();

        const uint32_t base = sb + (uint32_t)(c & 1) * 4 * TILEB;

#pragma unroll
        for (int kk = 0; kk < KCH; kk += 16) {
            uint32_t bhi[4][2], blo[4][2];
#pragma unroll
            for (int ni = 0; ni < 4; ni++) {
                const uint32_t baddr = base + 2 * TILEB
                    + (uint32_t)(wn * 32 + ni * 8 + (lane & 7)) * 80
                    + (uint32_t)(kk + ((lane >> 3) & 1) * 8) * 2;
                LDMX2(bhi[ni], baddr);
                LDMX2(blo[ni], baddr + TILEB);
            }
#pragma unroll
            for (int mi = 0; mi < 4; mi++) {
                const uint32_t aaddr = base
                    + (uint32_t)(wm * 64 + mi * 16 + (lane & 15)) * 80
                    + (uint32_t)(kk + (lane >> 4) * 8) * 2;
                uint32_t ah[4], al[4];
                LDMX4(ah, aaddr);
                LDMX4(al, aaddr + TILEB);
#pragma unroll
                for (int ni = 0; ni < 4; ni++) {
                    MMA_BF16(acc[mi][ni], ah, bhi[ni]);
                    MMA_BF16(acc[mi][ni], ah, blo[ni]);
                    MMA_BF16(acc[mi][ni], al, bhi[ni]);
                }
            }
        }
        __syncthreads();
    }

    // epilogue: fragment c0,c1 -> (row, col..col+1); c2,c3 -> (row+8, ...)
    const int rbase = bm + wm * 64 + (lane >> 2);
    const int cbase = bn + wn * 32 + (lane & 3) * 2;
#pragma unroll
    for (int mi = 0; mi < 4; mi++) {
#pragma unroll
        for (int ni = 0; ni < 4; ni++) {
            const int col = cbase + ni * 8;
            const float2 b2 = *(const float2*)(bias + col);
#pragma unroll
            for (int half = 0; half < 2; half++) {
                const int row = rbase + mi * 16 + half * 8;
                float2 o = make_float2(acc[mi][ni][half * 2 + 0] + b2.x,
                                       acc[mi][ni][half * 2 + 1] + b2.y);
                if (MODE == 3) {
                    *(float2*)(C + (size_t)row * HIDq + col) = o;
                } else {
                    const int b = row >> 10, s = row & 1023;
                    const int h = col >> 6,  d = col & 63;
                    *(float2*)(C + (((size_t)(b * NHq + h)) * Sq + s) * HDq + d) = o;
                }
            }
        }
    }
}

// ---------------------------------------------------------------------------
// Flash-style attention over one (b,h) with 64-row query tiles. (unchanged)
// ---------------------------------------------------------------------------
__global__ __launch_bounds__(256) void attn_kernel(const float* __restrict__ mask)
{
    extern __shared__ float smdyn[];
    float* Qs  = smdyn;                 // 64*65
    float* KVs = smdyn + 64 * 65;       // 64*65 (K, then reused for V)
    float* Ps  = smdyn + 2 * 64 * 65;   // 64*65

    const int bh = blockIdx.y;          // b*NH + h
    const int b = bh >> 4, h = bh & 15;
    const int qbase = blockIdx.x * 64;
    const int tid = threadIdx.x;
    const int tx = tid & 15, ty = tid >> 4;

    const float* Q  = g_q + (size_t)bh * Sq * HDq;
    const float* Kp = g_k + (size_t)bh * Sq * HDq;
    const float* Vp = g_v + (size_t)bh * Sq * HDq;

    for (int i = tid; i < 1024; i += 256) {
        const int r = i >> 4, c = (i & 15) << 2;
        float4 v = *(const float4*)(Q + (size_t)(qbase + r) * HDq + c);
        Qs[r * 65 + c + 0] = v.x; Qs[r * 65 + c + 1] = v.y;
        Qs[r * 65 + c + 2] = v.z; Qs[r * 65 + c + 3] = v.w;
    }

    float m_r[4], l_r[4], o[4][4];
#pragma unroll
    for (int i = 0; i < 4; i++) {
        m_r[i] = -1e30f; l_r[i] = 0.f;
#pragma unroll
        for (int j = 0; j < 4; j++) o[i][j] = 0.f;
    }
    __syncthreads();

    const float scale = 0.03125f;  // rsqrt(1024)

    for (int kt = 0; kt < Sq / 64; kt++) {
        const int kbase = kt * 64;

        for (int i = tid; i < 1024; i += 256) {
            const int r = i >> 4, c = (i & 15) << 2;
            float4 v = *(const float4*)(Kp + (size_t)(kbase + r) * HDq + c);
            KVs[r * 65 + c + 0] = v.x; KVs[r * 65 + c + 1] = v.y;
            KVs[r * 65 + c + 2] = v.z; KVs[r * 65 + c + 3] = v.w;
        }
        __syncthreads();

        float s[4][4];
#pragma unroll
        for (int i = 0; i < 4; i++)
#pragma unroll
            for (int j = 0; j < 4; j++) s[i][j] = 0.f;

#pragma unroll 8
        for (int d = 0; d < 64; d++) {
            float qv[4], kv[4];
#pragma unroll
            for (int i = 0; i < 4; i++) qv[i] = Qs[(ty * 4 + i) * 65 + d];
#pragma unroll
            for (int j = 0; j < 4; j++) kv[j] = KVs[(tx * 4 + j) * 65 + d];
#pragma unroll
            for (int i = 0; i < 4; i++)
#pragma unroll
                for (int j = 0; j < 4; j++)
                    s[i][j] = fmaf(qv[i], kv[j], s[i][j]);
        }

        const float* mp = mask + ((size_t)b * Sq + qbase + ty * 4) * Sq + kbase + tx * 4;
#pragma unroll
        for (int i = 0; i < 4; i++) {
            float4 mv = *(const float4*)(mp + (size_t)i * Sq);
            s[i][0] = fmaf(mv.x, -1e9f, s[i][0] * scale);
            s[i][1] = fmaf(mv.y, -1e9f, s[i][1] * scale);
            s[i][2] = fmaf(mv.z, -1e9f, s[i][2] * scale);
            s[i][3] = fmaf(mv.w, -1e9f, s[i][3] * scale);
        }

#pragma unroll
        for (int i = 0; i < 4; i++) {
            float mx = fmaxf(fmaxf(s[i][0], s[i][1]), fmaxf(s[i][2], s[i][3]));
            mx = fmaxf(mx, __shfl_xor_sync(0xffffffffu, mx, 1, 16));
            mx = fmaxf(mx, __shfl_xor_sync(0xffffffffu, mx, 2, 16));
            mx = fmaxf(mx, __shfl_xor_sync(0xffffffffu, mx, 4, 16));
            mx = fmaxf(mx, __shfl_xor_sync(0xffffffffu, mx, 8, 16));
            const float mnew  = fmaxf(m_r[i], mx);
            const float alpha = __expf(m_r[i] - mnew);
            float psum = 0.f;
#pragma unroll
            for (int j = 0; j < 4; j++) {
                const float p = __expf(s[i][j] - mnew);
                Ps[(ty * 4 + i) * 65 + tx * 4 + j] = p;
                psum += p;
            }
            psum += __shfl_xor_sync(0xffffffffu, psum, 1, 16);
            psum += __shfl_xor_sync(0xffffffffu, psum, 2, 16);
            psum += __shfl_xor_sync(0xffffffffu, psum, 4, 16);
            psum += __shfl_xor_sync(0xffffffffu, psum, 8, 16);
            l_r[i] = l_r[i] * alpha + psum;
            m_r[i] = mnew;
#pragma unroll
            for (int j = 0; j < 4; j++) o[i][j] *= alpha;
        }
        __syncthreads();

        for (int i = tid; i < 1024; i += 256) {
            const int r = i >> 4, c = (i & 15) << 2;
            float4 v = *(const float4*)(Vp + (size_t)(kbase + r) * HDq + c);
            KVs[r * 65 + c + 0] = v.x; KVs[r * 65 + c + 1] = v.y;
            KVs[r * 65 + c + 2] = v.z; KVs[r * 65 + c + 3] = v.w;
        }
        __syncthreads();

#pragma unroll 8
        for (int k = 0; k < 64; k++) {
            float pv[4], vv[4];
#pragma unroll
            for (int i = 0; i < 4; i++) pv[i] = Ps[(ty * 4 + i) * 65 + k];
#pragma unroll
            for (int j = 0; j < 4; j++) vv[j] = KVs[k * 65 + tx * 4 + j];
#pragma unroll
            for (int i = 0; i < 4; i++)
#pragma unroll
                for (int j = 0; j < 4; j++)
                    o[i][j] = fmaf(pv[i], vv[j], o[i][j]);
        }
        __syncthreads();
    }

#pragma unroll
    for (int i = 0; i < 4; i++) {
        const float inv = 1.0f / l_r[i];
        float4 ov = make_float4(o[i][0] * inv, o[i][1] * inv,
                                o[i][2] * inv, o[i][3] * inv);
        *(float4*)(g_ctx + ((size_t)(b * Sq + qbase + ty * 4 + i)) * HIDq
                   + h * HDq + tx * 4) = ov;
    }
}

// ---------------------------------------------------------------------------
extern "C" void kernel_launch(void* const* d_in, const int* in_sizes, int n_in,
                              void* d_out, int out_size)
{
    (void)in_sizes; (void)n_in; (void)out_size;
    const float* x   = (const float*)d_in[0];
    const float* msk = (const float*)d_in[1];
    const float* Wq  = (const float*)d_in[2];
    const float* bq  = (const float*)d_in[3];
    const float* Wk  = (const float*)d_in[4];
    const float* bk  = (const float*)d_in[5];
    const float* Wv  = (const float*)d_in[6];
    const float* bv  = (const float*)d_in[7];
    const float* Wp  = (const float*)d_in[8];
    const float* bp  = (const float*)d_in[9];
    float* out = (float*)d_out;

    cudaFuncSetAttribute(gemm_mma_kernel<0>, cudaFuncAttributeMaxDynamicSharedMemorySize, GSMEM);
    cudaFuncSetAttribute(gemm_mma_kernel<1>, cudaFuncAttributeMaxDynamicSharedMemorySize, GSMEM);
    cudaFuncSetAttribute(gemm_mma_kernel<2>, cudaFuncAttributeMaxDynamicSharedMemorySize, GSMEM);
    cudaFuncSetAttribute(gemm_mma_kernel<3>, cudaFuncAttributeMaxDynamicSharedMemorySize, GSMEM);
    const int attn_smem = 3 * 64 * 65 * (int)sizeof(float);  // 49920 B
    cudaFuncSetAttribute(attn_kernel, cudaFuncAttributeMaxDynamicSharedMemorySize, attn_smem);

    const dim3 cw(32, 32);
    const dim3 gg(HIDq / 128, Mq / 128);   // 8 x 64

    convert_x_kernel<false><<<(Mq * HIDq) / (256 * 8), 256>>>(x);

    convw_kernel<<<cw, 256>>>(Wq);
    gemm_mma_kernel<0><<<gg, 256, GSMEM>>>(bq, nullptr);
    convw_kernel<<<cw, 256>>>(Wk);
    gemm_mma_kernel<1><<<gg, 256, GSMEM>>>(bk, nullptr);
    convw_kernel<<<cw, 256>>>(Wv);
    gemm_mma_kernel<2><<<gg, 256, GSMEM>>>(bv, nullptr);

    attn_kernel<<<dim3(Sq / 64, Bq * NHq), 256, attn_smem>>>(msk);

    convert_x_kernel<true><<<(Mq * HIDq) / (256 * 8), 256>>>(x);
    convw_kernel<<<cw, 256>>>(Wp);
    gemm_mma_kernel<3><<<gg, 256, GSMEM>>>(bp, out);
}

// round 4
// speedup vs baseline: 1.9288x; 1.1398x over previous
#include <cuda_runtime.h>
#include <cuda_bf16.h>
#include <cstdint>

#define Bq   8
#define Sq   1024
#define HIDq 1024
#define NHq  16
#define HDq  64
#define Mq   (Bq * Sq)   // 8192

// Scratch (device globals: allocation-free per harness rules)
__device__ __nv_bfloat16 g_xhi[(size_t)Mq * HIDq];    // A operand hi [M,K] (x, later ctx)
__device__ __nv_bfloat16 g_xlo[(size_t)Mq * HIDq];
__device__ __nv_bfloat16 g_wthi[(size_t)HIDq * HIDq]; // W^T hi [N,K]
__device__ __nv_bfloat16 g_wtlo[(size_t)HIDq * HIDq];
__device__ __nv_bfloat16 g_qhi[(size_t)Bq * NHq * Sq * HDq];  // [B,NH,S,HD]
__device__ __nv_bfloat16 g_qlo[(size_t)Bq * NHq * Sq * HDq];
__device__ __nv_bfloat16 g_khi[(size_t)Bq * NHq * Sq * HDq];
__device__ __nv_bfloat16 g_klo[(size_t)Bq * NHq * Sq * HDq];
__device__ __nv_bfloat16 g_vhi[(size_t)Bq * NHq * Sq * HDq];
__device__ __nv_bfloat16 g_vlo[(size_t)Bq * NHq * Sq * HDq];

// ===========================================================================
// PTX helpers (portable tensor ISA: ldmatrix + mma.sync, sm_80+)
// ===========================================================================
__device__ __forceinline__ uint32_t smem_to_u32(const void* p) {
    uint32_t a;
    asm("{ .reg .u64 t; cvta.to.shared.u64 t, %1; cvt.u32.u64 %0, t; }"
        : "=r"(a) : "l"(p));
    return a;
}

#define LDMX4(r, addr) \
    asm volatile("ldmatrix.sync.aligned.m8n8.x4.shared.b16 {%0,%1,%2,%3}, [%4];" \
        : "=r"((r)[0]), "=r"((r)[1]), "=r"((r)[2]), "=r"((r)[3]) : "r"(addr))

#define LDMX2(r, addr) \
    asm volatile("ldmatrix.sync.aligned.m8n8.x2.shared.b16 {%0,%1}, [%2];" \
        : "=r"((r)[0]), "=r"((r)[1]) : "r"(addr))

#define LDMX2T(r, addr) \
    asm volatile("ldmatrix.sync.aligned.m8n8.x2.trans.shared.b16 {%0,%1}, [%2];" \
        : "=r"((r)[0]), "=r"((r)[1]) : "r"(addr))

#define MMA_BF16(d, a, b) \
    asm volatile("mma.sync.aligned.m16n8k16.row.col.f32.bf16.bf16.f32 " \
        "{%0,%1,%2,%3}, {%4,%5,%6,%7}, {%8,%9}, {%0,%1,%2,%3};" \
        : "+f"((d)[0]), "+f"((d)[1]), "+f"((d)[2]), "+f"((d)[3]) \
        : "r"((a)[0]), "r"((a)[1]), "r"((a)[2]), "r"((a)[3]), \
          "r"((b)[0]), "r"((b)[1]))

#define CP_ASYNC16(smem, gmem) \
    asm volatile("cp.async.cg.shared.global [%0], [%1], 16;" \
        :: "r"(smem), "l"(gmem) : "memory")
#define CP_COMMIT()  asm volatile("cp.async.commit_group;" ::: "memory")
#define CP_WAIT(n)   asm volatile("cp.async.wait_group %0;" :: "n"(n) : "memory")

// split f32 pair -> bf16x2 hi + bf16x2 lo
__device__ __forceinline__ void split2(float a, float b, uint32_t& hi, uint32_t& lo) {
    __nv_bfloat162 h = __floats2bfloat162_rn(a, b);
    uint32_t hu = *(uint32_t*)&h;
    float f0 = __uint_as_float(hu << 16);
    float f1 = __uint_as_float(hu & 0xFFFF0000u);
    __nv_bfloat162 l = __floats2bfloat162_rn(a - f0, b - f1);
    hi = hu;
    lo = *(uint32_t*)&l;
}

// ===========================================================================
// Conversion: x fp32 -> bf16 hi/lo split
// ===========================================================================
__global__ __launch_bounds__(256) void convert_x_kernel(const float* __restrict__ src)
{
    const size_t i = ((size_t)blockIdx.x * 256 + threadIdx.x) * 8;
    float4 v0 = *(const float4*)(src + i);
    float4 v1 = *(const float4*)(src + i + 4);
    float f[8] = {v0.x, v0.y, v0.z, v0.w, v1.x, v1.y, v1.z, v1.w};
    uint32_t hw[4], lw[4];
#pragma unroll
    for (int j = 0; j < 4; j++) split2(f[2 * j], f[2 * j + 1], hw[j], lw[j]);
    *(uint4*)(g_xhi + i) = make_uint4(hw[0], hw[1], hw[2], hw[3]);
    *(uint4*)(g_xlo + i) = make_uint4(lw[0], lw[1], lw[2], lw[3]);
}

// ===========================================================================
// Weight transpose + split: g_wt{hi,lo}[n][k] = split(W[k][n])
// ===========================================================================
__global__ __launch_bounds__(256) void convw_kernel(const float* __restrict__ W)
{
    __shared__ float tile[32][33];
    const int bx = blockIdx.x * 32, by = blockIdx.y * 32;
    const int tx = threadIdx.x & 31, ty = threadIdx.x >> 5;  // 32 x 8
#pragma unroll
    for (int i = 0; i < 4; i++)
        tile[ty + i * 8][tx] = W[(size_t)(by + ty + i * 8) * HIDq + bx + tx];
    __syncthreads();
#pragma unroll
    for (int i = 0; i < 4; i++) {
        const float v = tile[tx][ty + i * 8];
        const __nv_bfloat16 h = __float2bfloat16(v);
        const size_t o = (size_t)(bx + ty + i * 8) * HIDq + by + tx;
        g_wthi[o] = h;
        g_wtlo[o] = __float2bfloat16(v - __bfloat162float(h));
    }
}

// ===========================================================================
// 3x-bf16 mma.sync GEMM: C = A[8192,1024] @ W[1024,1024] + bias
// MODE 0/1/2: epilogue splits to (g_qhi,g_qlo)/(g_khi,g_klo)/(g_vhi,g_vlo)
//             scattered into [B,NH,S,HD]; MODE 3: fp32 row-major to d_out.
// ===========================================================================
#define KCH     32
#define TILEB   (128 * 40 * 2)          // 10240 B per tile (row stride 80 B)
#define GSMEM   (8 * TILEB)             // 81920 B

template <int MODE>
__global__ __launch_bounds__(256, 2) void gemm_mma_kernel(
    const float* __restrict__ bias, float* __restrict__ Cout)
{
    extern __shared__ char sm[];
    const uint32_t sb = smem_to_u32(sm);

    const int tid = threadIdx.x, lane = tid & 31, wid = tid >> 5;
    const int wm = wid >> 2, wn = wid & 3;             // 2 x 4 warp grid
    const int bm = blockIdx.y * 128, bn = blockIdx.x * 128;

    float acc[4][4][4];
#pragma unroll
    for (int mi = 0; mi < 4; mi++)
#pragma unroll
        for (int ni = 0; ni < 4; ni++)
#pragma unroll
            for (int r = 0; r < 4; r++) acc[mi][ni][r] = 0.f;

    const int g0 = tid, g1 = tid + 256;
    const int r0g = g0 >> 2, s0 = g0 & 3;
    const int r1g = g1 >> 2, s1 = g1 & 3;

    auto issue = [&](int c) {
        const int p = c & 1;
        const uint32_t base = sb + (uint32_t)p * 4 * TILEB;
        const int k0 = c * KCH;
        const uint32_t so0 = (uint32_t)r0g * 80 + (uint32_t)s0 * 16;
        const uint32_t so1 = (uint32_t)r1g * 80 + (uint32_t)s1 * 16;
        const size_t ga0 = (size_t)(bm + r0g) * HIDq + k0 + s0 * 8;
        const size_t ga1 = (size_t)(bm + r1g) * HIDq + k0 + s1 * 8;
        const size_t gb0 = (size_t)(bn + r0g) * HIDq + k0 + s0 * 8;
        const size_t gb1 = (size_t)(bn + r1g) * HIDq + k0 + s1 * 8;
        CP_ASYNC16(base + so0,             g_xhi  + ga0);
        CP_ASYNC16(base + so1,             g_xhi  + ga1);
        CP_ASYNC16(base + TILEB + so0,     g_xlo  + ga0);
        CP_ASYNC16(base + TILEB + so1,     g_xlo  + ga1);
        CP_ASYNC16(base + 2 * TILEB + so0, g_wthi + gb0);
        CP_ASYNC16(base + 2 * TILEB + so1, g_wthi + gb1);
        CP_ASYNC16(base + 3 * TILEB + so0, g_wtlo + gb0);
        CP_ASYNC16(base + 3 * TILEB + so1, g_wtlo + gb1);
        CP_COMMIT();
    };

    issue(0);

    for (int c = 0; c < HIDq / KCH; c++) {
        if (c + 1 < HIDq / KCH) { issue(c + 1); CP_WAIT(1); }
        else                    { CP_WAIT(0); }
        __syncthreads();

        const uint32_t base = sb + (uint32_t)(c & 1) * 4 * TILEB;

#pragma unroll
        for (int kk = 0; kk < KCH; kk += 16) {
            uint32_t bhi[4][2], blo[4][2];
#pragma unroll
            for (int ni = 0; ni < 4; ni++) {
                const uint32_t baddr = base + 2 * TILEB
                    + (uint32_t)(wn * 32 + ni * 8 + (lane & 7)) * 80
                    + (uint32_t)(kk + ((lane >> 3) & 1) * 8) * 2;
                LDMX2(bhi[ni], baddr);
                LDMX2(blo[ni], baddr + TILEB);
            }
#pragma unroll
            for (int mi = 0; mi < 4; mi++) {
                const uint32_t aaddr = base
                    + (uint32_t)(wm * 64 + mi * 16 + (lane & 15)) * 80
                    + (uint32_t)(kk + (lane >> 4) * 8) * 2;
                uint32_t ah[4], al[4];
                LDMX4(ah, aaddr);
                LDMX4(al, aaddr + TILEB);
#pragma unroll
                for (int ni = 0; ni < 4; ni++) {
                    MMA_BF16(acc[mi][ni], ah, bhi[ni]);
                    MMA_BF16(acc[mi][ni], ah, blo[ni]);
                    MMA_BF16(acc[mi][ni], al, bhi[ni]);
                }
            }
        }
        __syncthreads();
    }

    __nv_bfloat16* Chi = (MODE == 0) ? g_qhi : (MODE == 1) ? g_khi : g_vhi;
    __nv_bfloat16* Clo = (MODE == 0) ? g_qlo : (MODE == 1) ? g_klo : g_vlo;

    const int rbase = bm + wm * 64 + (lane >> 2);
    const int cbase = bn + wn * 32 + (lane & 3) * 2;
#pragma unroll
    for (int mi = 0; mi < 4; mi++) {
#pragma unroll
        for (int ni = 0; ni < 4; ni++) {
            const int col = cbase + ni * 8;
            const float2 b2 = *(const float2*)(bias + col);
#pragma unroll
            for (int half = 0; half < 2; half++) {
                const int row = rbase + mi * 16 + half * 8;
                const float ox = acc[mi][ni][half * 2 + 0] + b2.x;
                const float oy = acc[mi][ni][half * 2 + 1] + b2.y;
                if (MODE == 3) {
                    *(float2*)(Cout + (size_t)row * HIDq + col) = make_float2(ox, oy);
                } else {
                    const int b = row >> 10, s = row & 1023;
                    const int h = col >> 6,  d = col & 63;
                    const size_t off = (((size_t)(b * NHq + h)) * Sq + s) * HDq + d;
                    uint32_t hi, lo;
                    split2(ox, oy, hi, lo);
                    *(uint32_t*)(Chi + off) = hi;
                    *(uint32_t*)(Clo + off) = lo;
                }
            }
        }
    }
}

// ===========================================================================
// Tensor-core flash attention: per (b,h), 128-query tile, 128-key tiles.
// 256 threads = 8 warps, each warp owns 16 query rows.
// Scores & PV via 3-split bf16 mma.sync; softmax fp32 in fragments.
// ctx written as bf16 hi/lo straight into g_xhi/g_xlo [B*S, HID].
// ===========================================================================
#define ATILE 18432                      // 128 rows x 144 B (72 bf16 stride)
#define KVOFF (2 * ATILE)
#define ASMEM (10 * ATILE)               // Qhi,Qlo + 2 x (Khi,Klo,Vhi,Vlo)

__global__ __launch_bounds__(256, 1) void attn_mma_kernel(const float* __restrict__ mask)
{
    extern __shared__ char sm[];
    const uint32_t sb = smem_to_u32(sm);

    const int bh = blockIdx.y;
    const int b = bh >> 4, h = bh & 15;
    const int qbase = blockIdx.x * 128;
    const int tid = threadIdx.x, lane = tid & 31, wid = tid >> 5;
    const int wrow = wid * 16;

    const size_t hb = (size_t)bh * Sq * HDq;
    const __nv_bfloat16* Qhi = g_qhi + hb;
    const __nv_bfloat16* Qlo = g_qlo + hb;
    const __nv_bfloat16* KVg[4] = {g_khi + hb, g_klo + hb, g_vhi + hb, g_vlo + hb};

    // --- Q load (group 0 together with key-tile 0) ---
#pragma unroll
    for (int t = 0; t < 8; t++) {
        const int which = t >> 2;               // 0 = hi, 1 = lo
        const int id = (t & 3) * 256 + tid;     // 0..1023
        const int row = id >> 3, seg = id & 7;
        const __nv_bfloat16* src = (which ? Qlo : Qhi) + (size_t)(qbase + row) * HDq + seg * 8;
        CP_ASYNC16(sb + (uint32_t)which * ATILE + (uint32_t)row * 144 + seg * 16, src);
    }

    auto issue_kv = [&](int kt) {
        const uint32_t base = sb + KVOFF + (uint32_t)(kt & 1) * 4 * ATILE;
#pragma unroll
        for (int t = 0; t < 16; t++) {
            const int which = t >> 2;           // 0..3: Khi,Klo,Vhi,Vlo
            const int id = (t & 3) * 256 + tid;
            const int row = id >> 3, seg = id & 7;
            const __nv_bfloat16* src = KVg[which] + (size_t)(kt * 128 + row) * HDq + seg * 8;
            CP_ASYNC16(base + (uint32_t)which * ATILE + (uint32_t)row * 144 + seg * 16, src);
        }
        CP_COMMIT();
    };

    issue_kv(0);   // group 0: Q + KV0

    float m_st[2] = {-1e30f, -1e30f};
    float l_st[2] = {0.f, 0.f};
    float ctx[8][4];
#pragma unroll
    for (int n = 0; n < 8; n++)
#pragma unroll
        for (int r = 0; r < 4; r++) ctx[n][r] = 0.f;

    const float scale = 0.03125f;  // rsqrt(1024)
    const int r0 = qbase + wrow + (lane >> 2);   // global query row (and r0+8)

    for (int kt = 0; kt < Sq / 128; kt++) {
        if (kt + 1 < Sq / 128) { issue_kv(kt + 1); CP_WAIT(1); }
        else                   { CP_WAIT(0); }
        __syncthreads();

        const uint32_t kvb = sb + KVOFF + (uint32_t)(kt & 1) * 4 * ATILE;

        // ---- scores S = Q K^T (3-split) ----
        float accs[16][4];
#pragma unroll
        for (int n = 0; n < 16; n++)
#pragma unroll
            for (int r = 0; r < 4; r++) accs[n][r] = 0.f;

#pragma unroll
        for (int k0 = 0; k0 < 64; k0 += 16) {
            uint32_t ah[4], al[4];
            const uint32_t aaddr = sb + (uint32_t)(wrow + (lane & 15)) * 144
                                 + (uint32_t)(k0 + (lane >> 4) * 8) * 2;
            LDMX4(ah, aaddr);
            LDMX4(al, aaddr + ATILE);
#pragma unroll
            for (int n = 0; n < 16; n++) {
                const uint32_t baddr = kvb + (uint32_t)(n * 8 + (lane & 7)) * 144
                                     + (uint32_t)(k0 + ((lane >> 3) & 1) * 8) * 2;
                uint32_t bh2[2], bl2[2];
                LDMX2(bh2, baddr);
                LDMX2(bl2, baddr + ATILE);
                MMA_BF16(accs[n], ah, bh2);
                MMA_BF16(accs[n], ah, bl2);
                MMA_BF16(accs[n], al, bh2);
            }
        }

        // ---- scale + mask ----
        const float* mrow0 = mask + ((size_t)b * Sq + r0) * Sq + kt * 128 + (lane & 3) * 2;
        const float* mrow1 = mrow0 + 8 * Sq;
#pragma unroll
        for (int n = 0; n < 16; n++) {
            const float2 m0 = *(const float2*)(mrow0 + n * 8);
            const float2 m1 = *(const float2*)(mrow1 + n * 8);
            accs[n][0] = fmaf(m0.x, -1e9f, accs[n][0] * scale);
            accs[n][1] = fmaf(m0.y, -1e9f, accs[n][1] * scale);
            accs[n][2] = fmaf(m1.x, -1e9f, accs[n][2] * scale);
            accs[n][3] = fmaf(m1.y, -1e9f, accs[n][3] * scale);
        }

        // ---- online softmax (rows r0, r0+8) ----
        float mx0 = -1e30f, mx1 = -1e30f;
#pragma unroll
        for (int n = 0; n < 16; n++) {
            mx0 = fmaxf(mx0, fmaxf(accs[n][0], accs[n][1]));
            mx1 = fmaxf(mx1, fmaxf(accs[n][2], accs[n][3]));
        }
        mx0 = fmaxf(mx0, __shfl_xor_sync(0xffffffffu, mx0, 1));
        mx0 = fmaxf(mx0, __shfl_xor_sync(0xffffffffu, mx0, 2));
        mx1 = fmaxf(mx1, __shfl_xor_sync(0xffffffffu, mx1, 1));
        mx1 = fmaxf(mx1, __shfl_xor_sync(0xffffffffu, mx1, 2));

        const float mn0 = fmaxf(m_st[0], mx0);
        const float mn1 = fmaxf(m_st[1], mx1);
        const float al0 = __expf(m_st[0] - mn0);
        const float al1 = __expf(m_st[1] - mn1);
        m_st[0] = mn0; m_st[1] = mn1;

        float sum0 = 0.f, sum1 = 0.f;
#pragma unroll
        for (int n = 0; n < 16; n++) {
            accs[n][0] = __expf(accs[n][0] - mn0);
            accs[n][1] = __expf(accs[n][1] - mn0);
            accs[n][2] = __expf(accs[n][2] - mn1);
            accs[n][3] = __expf(accs[n][3] - mn1);
            sum0 += accs[n][0] + accs[n][1];
            sum1 += accs[n][2] + accs[n][3];
        }
        sum0 += __shfl_xor_sync(0xffffffffu, sum0, 1);
        sum0 += __shfl_xor_sync(0xffffffffu, sum0, 2);
        sum1 += __shfl_xor_sync(0xffffffffu, sum1, 1);
        sum1 += __shfl_xor_sync(0xffffffffu, sum1, 2);
        l_st[0] = l_st[0] * al0 + sum0;
        l_st[1] = l_st[1] * al1 + sum1;

#pragma unroll
        for (int n = 0; n < 8; n++) {
            ctx[n][0] *= al0; ctx[n][1] *= al0;
            ctx[n][2] *= al1; ctx[n][3] *= al1;
        }

        // ---- PV: ctx += P @ V (3-split, V via trans ldmatrix) ----
        const uint32_t vbase = kvb + 2 * ATILE;
#pragma unroll
        for (int kk2 = 0; kk2 < 8; kk2++) {
            uint32_t phi[4], plo[4];
            split2(accs[2 * kk2][0],     accs[2 * kk2][1],     phi[0], plo[0]);
            split2(accs[2 * kk2][2],     accs[2 * kk2][3],     phi[1], plo[1]);
            split2(accs[2 * kk2 + 1][0], accs[2 * kk2 + 1][1], phi[2], plo[2]);
            split2(accs[2 * kk2 + 1][2], accs[2 * kk2 + 1][3], phi[3], plo[3]);
#pragma unroll
            for (int n = 0; n < 8; n++) {
                const uint32_t vaddr = vbase + (uint32_t)(kk2 * 16 + (lane & 15)) * 144
                                     + (uint32_t)n * 16;
                uint32_t vh[2], vl[2];
                LDMX2T(vh, vaddr);
                LDMX2T(vl, vaddr + ATILE);
                MMA_BF16(ctx[n], phi, vh);
                MMA_BF16(ctx[n], phi, vl);
                MMA_BF16(ctx[n], plo, vh);
            }
        }
        __syncthreads();
    }

    // ---- epilogue: ctx / l -> bf16 hi/lo into g_xhi/g_xlo [B*S, HID] ----
    const float inv0 = 1.0f / l_st[0];
    const float inv1 = 1.0f / l_st[1];
    const int cb = h * HDq + (lane & 3) * 2;
#pragma unroll
    for (int n = 0; n < 8; n++) {
        const int col = cb + n * 8;
        const size_t off0 = ((size_t)(b * Sq + r0)) * HIDq + col;
        const size_t off1 = ((size_t)(b * Sq + r0 + 8)) * HIDq + col;
        uint32_t hi, lo;
        split2(ctx[n][0] * inv0, ctx[n][1] * inv0, hi, lo);
        *(uint32_t*)(g_xhi + off0) = hi;
        *(uint32_t*)(g_xlo + off0) = lo;
        split2(ctx[n][2] * inv1, ctx[n][3] * inv1, hi, lo);
        *(uint32_t*)(g_xhi + off1) = hi;
        *(uint32_t*)(g_xlo + off1) = lo;
    }
}

// ---------------------------------------------------------------------------
extern "C" void kernel_launch(void* const* d_in, const int* in_sizes, int n_in,
                              void* d_out, int out_size)
{
    (void)in_sizes; (void)n_in; (void)out_size;
    const float* x   = (const float*)d_in[0];
    const float* msk = (const float*)d_in[1];
    const float* Wq  = (const float*)d_in[2];
    const float* bq  = (const float*)d_in[3];
    const float* Wk  = (const float*)d_in[4];
    const float* bk  = (const float*)d_in[5];
    const float* Wv  = (const float*)d_in[6];
    const float* bv  = (const float*)d_in[7];
    const float* Wp  = (const float*)d_in[8];
    const float* bp  = (const float*)d_in[9];
    float* out = (float*)d_out;

    cudaFuncSetAttribute(gemm_mma_kernel<0>, cudaFuncAttributeMaxDynamicSharedMemorySize, GSMEM);
    cudaFuncSetAttribute(gemm_mma_kernel<1>, cudaFuncAttributeMaxDynamicSharedMemorySize, GSMEM);
    cudaFuncSetAttribute(gemm_mma_kernel<2>, cudaFuncAttributeMaxDynamicSharedMemorySize, GSMEM);
    cudaFuncSetAttribute(gemm_mma_kernel<3>, cudaFuncAttributeMaxDynamicSharedMemorySize, GSMEM);
    cudaFuncSetAttribute(attn_mma_kernel, cudaFuncAttributeMaxDynamicSharedMemorySize, ASMEM);

    const dim3 cw(32, 32);
    const dim3 gg(HIDq / 128, Mq / 128);   // 8 x 64

    convert_x_kernel<<<(Mq * HIDq) / (256 * 8), 256>>>(x);

    convw_kernel<<<cw, 256>>>(Wq);
    gemm_mma_kernel<0><<<gg, 256, GSMEM>>>(bq, nullptr);
    convw_kernel<<<cw, 256>>>(Wk);
    gemm_mma_kernel<1><<<gg, 256, GSMEM>>>(bk, nullptr);
    convw_kernel<<<cw, 256>>>(Wv);
    gemm_mma_kernel<2><<<gg, 256, GSMEM>>>(bv, nullptr);

    attn_mma_kernel<<<dim3(Sq / 128, Bq * NHq), 256, ASMEM>>>(msk);

    convw_kernel<<<cw, 256>>>(Wp);
    gemm_mma_kernel<3><<<gg, 256, GSMEM>>>(bp, out);
}

// round 5
// speedup vs baseline: 3.2413x; 1.6805x over previous
#include <cuda_runtime.h>
#include <cuda_bf16.h>
#include <cuda_fp16.h>
#include <cstdint>

#define Bq   8
#define Sq   1024
#define HIDq 1024
#define NHq  16
#define HDq  64
#define Mq   (Bq * Sq)   // 8192

// Scratch (device globals: allocation-free per harness rules)
__device__ __nv_bfloat16 g_xhi[(size_t)Mq * HIDq];    // A operand hi [M,K] (x, later ctx)
__device__ __nv_bfloat16 g_xlo[(size_t)Mq * HIDq];
__device__ __nv_bfloat16 g_wthi[(size_t)HIDq * HIDq]; // W^T hi [N,K]
__device__ __nv_bfloat16 g_wtlo[(size_t)HIDq * HIDq];
__device__ __half g_qhi[(size_t)Bq * NHq * Sq * HDq];  // [B,NH,S,HD] (pre-scaled)
__device__ __half g_qlo[(size_t)Bq * NHq * Sq * HDq];
__device__ __half g_khi[(size_t)Bq * NHq * Sq * HDq];  // single-term fp16
__device__ __half g_vhi[(size_t)Bq * NHq * Sq * HDq];
__device__ __half g_vlo[(size_t)Bq * NHq * Sq * HDq];

// ===========================================================================
// PTX helpers (portable tensor ISA: ldmatrix + mma.sync, sm_80+)
// ===========================================================================
__device__ __forceinline__ uint32_t smem_to_u32(const void* p) {
    uint32_t a;
    asm("{ .reg .u64 t; cvta.to.shared.u64 t, %1; cvt.u32.u64 %0, t; }"
        : "=r"(a) : "l"(p));
    return a;
}

#define LDMX4(r, addr) \
    asm volatile("ldmatrix.sync.aligned.m8n8.x4.shared.b16 {%0,%1,%2,%3}, [%4];" \
        : "=r"((r)[0]), "=r"((r)[1]), "=r"((r)[2]), "=r"((r)[3]) : "r"(addr))

#define LDMX2(r, addr) \
    asm volatile("ldmatrix.sync.aligned.m8n8.x2.shared.b16 {%0,%1}, [%2];" \
        : "=r"((r)[0]), "=r"((r)[1]) : "r"(addr))

#define LDMX2T(r, addr) \
    asm volatile("ldmatrix.sync.aligned.m8n8.x2.trans.shared.b16 {%0,%1}, [%2];" \
        : "=r"((r)[0]), "=r"((r)[1]) : "r"(addr))

#define MMA_BF16(d, a, b) \
    asm volatile("mma.sync.aligned.m16n8k16.row.col.f32.bf16.bf16.f32 " \
        "{%0,%1,%2,%3}, {%4,%5,%6,%7}, {%8,%9}, {%0,%1,%2,%3};" \
        : "+f"((d)[0]), "+f"((d)[1]), "+f"((d)[2]), "+f"((d)[3]) \
        : "r"((a)[0]), "r"((a)[1]), "r"((a)[2]), "r"((a)[3]), \
          "r"((b)[0]), "r"((b)[1]))

#define MMA_F16(d, a, b) \
    asm volatile("mma.sync.aligned.m16n8k16.row.col.f32.f16.f16.f32 " \
        "{%0,%1,%2,%3}, {%4,%5,%6,%7}, {%8,%9}, {%0,%1,%2,%3};" \
        : "+f"((d)[0]), "+f"((d)[1]), "+f"((d)[2]), "+f"((d)[3]) \
        : "r"((a)[0]), "r"((a)[1]), "r"((a)[2]), "r"((a)[3]), \
          "r"((b)[0]), "r"((b)[1]))

#define CP_ASYNC16(smem, gmem) \
    asm volatile("cp.async.cg.shared.global [%0], [%1], 16;" \
        :: "r"(smem), "l"(gmem) : "memory")
#define CP_COMMIT()  asm volatile("cp.async.commit_group;" ::: "memory")
#define CP_WAIT(n)   asm volatile("cp.async.wait_group %0;" :: "n"(n) : "memory")

// split f32 pair -> bf16x2 hi + bf16x2 lo
__device__ __forceinline__ void split2(float a, float b, uint32_t& hi, uint32_t& lo) {
    __nv_bfloat162 h = __floats2bfloat162_rn(a, b);
    uint32_t hu = *(uint32_t*)&h;
    float f0 = __uint_as_float(hu << 16);
    float f1 = __uint_as_float(hu & 0xFFFF0000u);
    __nv_bfloat162 l = __floats2bfloat162_rn(a - f0, b - f1);
    hi = hu;
    lo = *(uint32_t*)&l;
}

// split f32 pair -> fp16x2 hi + fp16x2 lo
__device__ __forceinline__ void split2h(float a, float b, uint32_t& hi, uint32_t& lo) {
    __half2 h = __floats2half2_rn(a, b);
    float f0 = __half2float(__low2half(h));
    float f1 = __half2float(__high2half(h));
    __half2 l = __floats2half2_rn(a - f0, b - f1);
    hi = *(uint32_t*)&h;
    lo = *(uint32_t*)&l;
}

// ===========================================================================
// Conversion: x fp32 -> bf16 hi/lo split
// ===========================================================================
__global__ __launch_bounds__(256) void convert_x_kernel(const float* __restrict__ src)
{
    const size_t i = ((size_t)blockIdx.x * 256 + threadIdx.x) * 8;
    float4 v0 = *(const float4*)(src + i);
    float4 v1 = *(const float4*)(src + i + 4);
    float f[8] = {v0.x, v0.y, v0.z, v0.w, v1.x, v1.y, v1.z, v1.w};
    uint32_t hw[4], lw[4];
#pragma unroll
    for (int j = 0; j < 4; j++) split2(f[2 * j], f[2 * j + 1], hw[j], lw[j]);
    *(uint4*)(g_xhi + i) = make_uint4(hw[0], hw[1], hw[2], hw[3]);
    *(uint4*)(g_xlo + i) = make_uint4(lw[0], lw[1], lw[2], lw[3]);
}

// ===========================================================================
// Weight transpose + split: g_wt{hi,lo}[n][k] = split(W[k][n])
// ===========================================================================
__global__ __launch_bounds__(256) void convw_kernel(const float* __restrict__ W)
{
    __shared__ float tile[32][33];
    const int bx = blockIdx.x * 32, by = blockIdx.y * 32;
    const int tx = threadIdx.x & 31, ty = threadIdx.x >> 5;  // 32 x 8
#pragma unroll
    for (int i = 0; i < 4; i++)
        tile[ty + i * 8][tx] = W[(size_t)(by + ty + i * 8) * HIDq + bx + tx];
    __syncthreads();
#pragma unroll
    for (int i = 0; i < 4; i++) {
        const float v = tile[tx][ty + i * 8];
        const __nv_bfloat16 h = __float2bfloat16(v);
        const size_t o = (size_t)(bx + ty + i * 8) * HIDq + by + tx;
        g_wthi[o] = h;
        g_wtlo[o] = __float2bfloat16(v - __bfloat162float(h));
    }
}

// ===========================================================================
// 3x-bf16 mma.sync GEMM: C = A[8192,1024] @ W[1024,1024] + bias
// MODE 0: fp16 hi/lo split, pre-scaled by rsqrt(HID), -> g_qhi/g_qlo
// MODE 1: fp16 single                              -> g_khi
// MODE 2: fp16 hi/lo split                         -> g_vhi/g_vlo
// MODE 3: fp32 row-major                           -> d_out
// ===========================================================================
#define KCH     32
#define TILEB   (128 * 40 * 2)          // 10240 B per tile (row stride 80 B)
#define GSMEM   (8 * TILEB)             // 81920 B

template <int MODE>
__global__ __launch_bounds__(256, 2) void gemm_mma_kernel(
    const float* __restrict__ bias, float* __restrict__ Cout)
{
    extern __shared__ char sm[];
    const uint32_t sb = smem_to_u32(sm);

    const int tid = threadIdx.x, lane = tid & 31, wid = tid >> 5;
    const int wm = wid >> 2, wn = wid & 3;             // 2 x 4 warp grid
    const int bm = blockIdx.y * 128, bn = blockIdx.x * 128;

    float acc[4][4][4];
#pragma unroll
    for (int mi = 0; mi < 4; mi++)
#pragma unroll
        for (int ni = 0; ni < 4; ni++)
#pragma unroll
            for (int r = 0; r < 4; r++) acc[mi][ni][r] = 0.f;

    const int g0 = tid, g1 = tid + 256;
    const int r0g = g0 >> 2, s0 = g0 & 3;
    const int r1g = g1 >> 2, s1 = g1 & 3;

    auto issue = [&](int c) {
        const int p = c & 1;
        const uint32_t base = sb + (uint32_t)p * 4 * TILEB;
        const int k0 = c * KCH;
        const uint32_t so0 = (uint32_t)r0g * 80 + (uint32_t)s0 * 16;
        const uint32_t so1 = (uint32_t)r1g * 80 + (uint32_t)s1 * 16;
        const size_t ga0 = (size_t)(bm + r0g) * HIDq + k0 + s0 * 8;
        const size_t ga1 = (size_t)(bm + r1g) * HIDq + k0 + s1 * 8;
        const size_t gb0 = (size_t)(bn + r0g) * HIDq + k0 + s0 * 8;
        const size_t gb1 = (size_t)(bn + r1g) * HIDq + k0 + s1 * 8;
        CP_ASYNC16(base + so0,             g_xhi  + ga0);
        CP_ASYNC16(base + so1,             g_xhi  + ga1);
        CP_ASYNC16(base + TILEB + so0,     g_xlo  + ga0);
        CP_ASYNC16(base + TILEB + so1,     g_xlo  + ga1);
        CP_ASYNC16(base + 2 * TILEB + so0, g_wthi + gb0);
        CP_ASYNC16(base + 2 * TILEB + so1, g_wthi + gb1);
        CP_ASYNC16(base + 3 * TILEB + so0, g_wtlo + gb0);
        CP_ASYNC16(base + 3 * TILEB + so1, g_wtlo + gb1);
        CP_COMMIT();
    };

    issue(0);

    for (int c = 0; c < HIDq / KCH; c++) {
        if (c + 1 < HIDq / KCH) { issue(c + 1); CP_WAIT(1); }
        else                    { CP_WAIT(0); }
        __syncthreads();

        const uint32_t base = sb + (uint32_t)(c & 1) * 4 * TILEB;

#pragma unroll
        for (int kk = 0; kk < KCH; kk += 16) {
            uint32_t bhi[4][2], blo[4][2];
#pragma unroll
            for (int ni = 0; ni < 4; ni++) {
                const uint32_t baddr = base + 2 * TILEB
                    + (uint32_t)(wn * 32 + ni * 8 + (lane & 7)) * 80
                    + (uint32_t)(kk + ((lane >> 3) & 1) * 8) * 2;
                LDMX2(bhi[ni], baddr);
                LDMX2(blo[ni], baddr + TILEB);
            }
#pragma unroll
            for (int mi = 0; mi < 4; mi++) {
                const uint32_t aaddr = base
                    + (uint32_t)(wm * 64 + mi * 16 + (lane & 15)) * 80
                    + (uint32_t)(kk + (lane >> 4) * 8) * 2;
                uint32_t ah[4], al[4];
                LDMX4(ah, aaddr);
                LDMX4(al, aaddr + TILEB);
#pragma unroll
                for (int ni = 0; ni < 4; ni++) {
                    MMA_BF16(acc[mi][ni], ah, bhi[ni]);
                    MMA_BF16(acc[mi][ni], ah, blo[ni]);
                    MMA_BF16(acc[mi][ni], al, bhi[ni]);
                }
            }
        }
        __syncthreads();
    }

    const int rbase = bm + wm * 64 + (lane >> 2);
    const int cbase = bn + wn * 32 + (lane & 3) * 2;
#pragma unroll
    for (int mi = 0; mi < 4; mi++) {
#pragma unroll
        for (int ni = 0; ni < 4; ni++) {
            const int col = cbase + ni * 8;
            const float2 b2 = *(const float2*)(bias + col);
#pragma unroll
            for (int half = 0; half < 2; half++) {
                const int row = rbase + mi * 16 + half * 8;
                float ox = acc[mi][ni][half * 2 + 0] + b2.x;
                float oy = acc[mi][ni][half * 2 + 1] + b2.y;
                if (MODE == 3) {
                    *(float2*)(Cout + (size_t)row * HIDq + col) = make_float2(ox, oy);
                } else {
                    const int b = row >> 10, s = row & 1023;
                    const int h = col >> 6,  d = col & 63;
                    const size_t off = (((size_t)(b * NHq + h)) * Sq + s) * HDq + d;
                    if (MODE == 0) {
                        uint32_t hi, lo;
                        split2h(ox * 0.03125f, oy * 0.03125f, hi, lo);
                        *(uint32_t*)(g_qhi + off) = hi;
                        *(uint32_t*)(g_qlo + off) = lo;
                    } else if (MODE == 1) {
                        __half2 h2 = __floats2half2_rn(ox, oy);
                        *(uint32_t*)(g_khi + off) = *(uint32_t*)&h2;
                    } else {
                        uint32_t hi, lo;
                        split2h(ox, oy, hi, lo);
                        *(uint32_t*)(g_vhi + off) = hi;
                        *(uint32_t*)(g_vlo + off) = lo;
                    }
                }
            }
        }
    }
}

// ===========================================================================
// fp16 flash attention: per (b,h), 128-query tile, 64-key stages (2-stage).
// 256 threads = 8 warps, warp owns 16 query rows.
// Scores: (Qhi+Qlo)*Khi (2 MMA); PV: P_fp16*(Vhi+Vlo) (2 MMA).
// smem 90 KB -> 2 CTAs/SM. ctx -> bf16 hi/lo into g_xhi/g_xlo [B*S, HID].
// ===========================================================================
#define QTILE  18432                    // 128 rows x 144 B
#define KVTILE 9216                     // 64 rows x 144 B
#define KVSTG  (3 * KVTILE)             // Khi, Vhi, Vlo
#define KVOFF  (2 * QTILE)
#define ASMEM  (KVOFF + 2 * KVSTG)      // 92160
#define NTK    (Sq / 64)                // 16

__global__ __launch_bounds__(256, 2) void attn_mma_kernel(const float* __restrict__ mask)
{
    extern __shared__ char sm[];
    const uint32_t sb = smem_to_u32(sm);

    const int bh = blockIdx.y;
    const int b = bh >> 4, h = bh & 15;
    const int qbase = blockIdx.x * 128;
    const int tid = threadIdx.x, lane = tid & 31, wid = tid >> 5;
    const int wrow = wid * 16;

    const size_t hb = (size_t)bh * Sq * HDq;
    const __half* Qhi = g_qhi + hb;
    const __half* Qlo = g_qlo + hb;
    const __half* KVg[3] = {g_khi + hb, g_vhi + hb, g_vlo + hb};

    // Q load (joins cp.async group 0 with KV stage 0)
#pragma unroll
    for (int t = 0; t < 8; t++) {
        const int which = t >> 2;               // 0 = hi, 1 = lo
        const int id = (t & 3) * 256 + tid;
        const int row = id >> 3, seg = id & 7;
        const __half* src = (which ? Qlo : Qhi) + (size_t)(qbase + row) * HDq + seg * 8;
        CP_ASYNC16(sb + (uint32_t)which * QTILE + (uint32_t)row * 144 + seg * 16, src);
    }

    auto issue_kv = [&](int kt) {
        const uint32_t base = sb + KVOFF + (uint32_t)(kt & 1) * KVSTG;
#pragma unroll
        for (int t = 0; t < 6; t++) {
            const int which = t >> 1;           // 0=Khi, 1=Vhi, 2=Vlo
            const int id = (t & 1) * 256 + tid;
            const int row = id >> 3, seg = id & 7;
            CP_ASYNC16(base + (uint32_t)which * KVTILE + (uint32_t)row * 144 + seg * 16,
                       KVg[which] + (size_t)(kt * 64 + row) * HDq + seg * 8);
        }
        CP_COMMIT();
    };

    issue_kv(0);

    float m_st[2] = {-1e30f, -1e30f};
    float l_st[2] = {0.f, 0.f};
    float ctx[8][4];
#pragma unroll
    for (int n = 0; n < 8; n++)
#pragma unroll
        for (int r = 0; r < 4; r++) ctx[n][r] = 0.f;

    const int r0 = qbase + wrow + (lane >> 2);

    for (int kt = 0; kt < NTK; kt++) {
        if (kt + 1 < NTK) { issue_kv(kt + 1); CP_WAIT(1); }
        else              { CP_WAIT(0); }
        __syncthreads();

        const uint32_t kvb = sb + KVOFF + (uint32_t)(kt & 1) * KVSTG;

        // ---- scores S = (Qhi+Qlo) Khi^T ----
        float accs[8][4];
#pragma unroll
        for (int n = 0; n < 8; n++)
#pragma unroll
            for (int r = 0; r < 4; r++) accs[n][r] = 0.f;

#pragma unroll
        for (int k0 = 0; k0 < 64; k0 += 16) {
            uint32_t ah[4], al[4];
            const uint32_t aaddr = sb + (uint32_t)(wrow + (lane & 15)) * 144
                                 + (uint32_t)(k0 + (lane >> 4) * 8) * 2;
            LDMX4(ah, aaddr);
            LDMX4(al, aaddr + QTILE);
#pragma unroll
            for (int n = 0; n < 8; n++) {
                const uint32_t baddr = kvb + (uint32_t)(n * 8 + (lane & 7)) * 144
                                     + (uint32_t)(k0 + ((lane >> 3) & 1) * 8) * 2;
                uint32_t kb[2];
                LDMX2(kb, baddr);
                MMA_F16(accs[n], ah, kb);
                MMA_F16(accs[n], al, kb);
            }
        }

        // ---- mask (scale already folded into Q) ----
        const float* mrow0 = mask + ((size_t)b * Sq + r0) * Sq + kt * 64 + (lane & 3) * 2;
        const float* mrow1 = mrow0 + 8 * Sq;
#pragma unroll
        for (int n = 0; n < 8; n++) {
            const float2 m0 = *(const float2*)(mrow0 + n * 8);
            const float2 m1 = *(const float2*)(mrow1 + n * 8);
            accs[n][0] = fmaf(m0.x, -1e9f, accs[n][0]);
            accs[n][1] = fmaf(m0.y, -1e9f, accs[n][1]);
            accs[n][2] = fmaf(m1.x, -1e9f, accs[n][2]);
            accs[n][3] = fmaf(m1.y, -1e9f, accs[n][3]);
        }

        // ---- online softmax (rows r0, r0+8) ----
        float mx0 = -1e30f, mx1 = -1e30f;
#pragma unroll
        for (int n = 0; n < 8; n++) {
            mx0 = fmaxf(mx0, fmaxf(accs[n][0], accs[n][1]));
            mx1 = fmaxf(mx1, fmaxf(accs[n][2], accs[n][3]));
        }
        mx0 = fmaxf(mx0, __shfl_xor_sync(0xffffffffu, mx0, 1));
        mx0 = fmaxf(mx0, __shfl_xor_sync(0xffffffffu, mx0, 2));
        mx1 = fmaxf(mx1, __shfl_xor_sync(0xffffffffu, mx1, 1));
        mx1 = fmaxf(mx1, __shfl_xor_sync(0xffffffffu, mx1, 2));

        const float mn0 = fmaxf(m_st[0], mx0);
        const float mn1 = fmaxf(m_st[1], mx1);
        const float al0 = __expf(m_st[0] - mn0);
        const float al1 = __expf(m_st[1] - mn1);
        m_st[0] = mn0; m_st[1] = mn1;

        float sum0 = 0.f, sum1 = 0.f;
#pragma unroll
        for (int n = 0; n < 8; n++) {
            accs[n][0] = __expf(accs[n][0] - mn0);
            accs[n][1] = __expf(accs[n][1] - mn0);
            accs[n][2] = __expf(accs[n][2] - mn1);
            accs[n][3] = __expf(accs[n][3] - mn1);
            sum0 += accs[n][0] + accs[n][1];
            sum1 += accs[n][2] + accs[n][3];
        }
        sum0 += __shfl_xor_sync(0xffffffffu, sum0, 1);
        sum0 += __shfl_xor_sync(0xffffffffu, sum0, 2);
        sum1 += __shfl_xor_sync(0xffffffffu, sum1, 1);
        sum1 += __shfl_xor_sync(0xffffffffu, sum1, 2);
        l_st[0] = l_st[0] * al0 + sum0;
        l_st[1] = l_st[1] * al1 + sum1;

#pragma unroll
        for (int n = 0; n < 8; n++) {
            ctx[n][0] *= al0; ctx[n][1] *= al0;
            ctx[n][2] *= al1; ctx[n][3] *= al1;
        }

        // ---- PV: ctx += P_fp16 (Vhi + Vlo) ----
        const uint32_t vbase = kvb + KVTILE;
#pragma unroll
        for (int kk2 = 0; kk2 < 4; kk2++) {
            uint32_t pf[4];
            __half2 p0 = __floats2half2_rn(accs[2 * kk2][0],     accs[2 * kk2][1]);
            __half2 p1 = __floats2half2_rn(accs[2 * kk2][2],     accs[2 * kk2][3]);
            __half2 p2 = __floats2half2_rn(accs[2 * kk2 + 1][0], accs[2 * kk2 + 1][1]);
            __half2 p3 = __floats2half2_rn(accs[2 * kk2 + 1][2], accs[2 * kk2 + 1][3]);
            pf[0] = *(uint32_t*)&p0; pf[1] = *(uint32_t*)&p1;
            pf[2] = *(uint32_t*)&p2; pf[3] = *(uint32_t*)&p3;
#pragma unroll
            for (int n = 0; n < 8; n++) {
                const uint32_t vaddr = vbase + (uint32_t)(kk2 * 16 + (lane & 15)) * 144
                                     + (uint32_t)n * 16;
                uint32_t vh[2], vl[2];
                LDMX2T(vh, vaddr);
                LDMX2T(vl, vaddr + KVTILE);
                MMA_F16(ctx[n], pf, vh);
                MMA_F16(ctx[n], pf, vl);
            }
        }
        __syncthreads();
    }

    // ---- epilogue: ctx / l -> bf16 hi/lo into g_xhi/g_xlo [B*S, HID] ----
    const float inv0 = 1.0f / l_st[0];
    const float inv1 = 1.0f / l_st[1];
    const int cb = h * HDq + (lane & 3) * 2;
#pragma unroll
    for (int n = 0; n < 8; n++) {
        const int col = cb + n * 8;
        const size_t off0 = ((size_t)(b * Sq + r0)) * HIDq + col;
        const size_t off1 = ((size_t)(b * Sq + r0 + 8)) * HIDq + col;
        uint32_t hi, lo;
        split2(ctx[n][0] * inv0, ctx[n][1] * inv0, hi, lo);
        *(uint32_t*)(g_xhi + off0) = hi;
        *(uint32_t*)(g_xlo + off0) = lo;
        split2(ctx[n][2] * inv1, ctx[n][3] * inv1, hi, lo);
        *(uint32_t*)(g_xhi + off1) = hi;
        *(uint32_t*)(g_xlo + off1) = lo;
    }
}

// ---------------------------------------------------------------------------
extern "C" void kernel_launch(void* const* d_in, const int* in_sizes, int n_in,
                              void* d_out, int out_size)
{
    (void)in_sizes; (void)n_in; (void)out_size;
    const float* x   = (const float*)d_in[0];
    const float* msk = (const float*)d_in[1];
    const float* Wq  = (const float*)d_in[2];
    const float* bq  = (const float*)d_in[3];
    const float* Wk  = (const float*)d_in[4];
    const float* bk  = (const float*)d_in[5];
    const float* Wv  = (const float*)d_in[6];
    const float* bv  = (const float*)d_in[7];
    const float* Wp  = (const float*)d_in[8];
    const float* bp  = (const float*)d_in[9];
    float* out = (float*)d_out;

    cudaFuncSetAttribute(gemm_mma_kernel<0>, cudaFuncAttributeMaxDynamicSharedMemorySize, GSMEM);
    cudaFuncSetAttribute(gemm_mma_kernel<1>, cudaFuncAttributeMaxDynamicSharedMemorySize, GSMEM);
    cudaFuncSetAttribute(gemm_mma_kernel<2>, cudaFuncAttributeMaxDynamicSharedMemorySize, GSMEM);
    cudaFuncSetAttribute(gemm_mma_kernel<3>, cudaFuncAttributeMaxDynamicSharedMemorySize, GSMEM);
    cudaFuncSetAttribute(attn_mma_kernel, cudaFuncAttributeMaxDynamicSharedMemorySize, ASMEM);

    const dim3 cw(32, 32);
    const dim3 gg(HIDq / 128, Mq / 128);   // 8 x 64

    convert_x_kernel<<<(Mq * HIDq) / (256 * 8), 256>>>(x);

    convw_kernel<<<cw, 256>>>(Wq);
    gemm_mma_kernel<0><<<gg, 256, GSMEM>>>(bq, nullptr);
    convw_kernel<<<cw, 256>>>(Wk);
    gemm_mma_kernel<1><<<gg, 256, GSMEM>>>(bk, nullptr);
    convw_kernel<<<cw, 256>>>(Wv);
    gemm_mma_kernel<2><<<gg, 256, GSMEM>>>(bv, nullptr);

    attn_mma_kernel<<<dim3(Sq / 128, Bq * NHq), 256, ASMEM>>>(msk);

    convw_kernel<<<cw, 256>>>(Wp);
    gemm_mma_kernel<3><<<gg, 256, GSMEM>>>(bp, out);
}

// round 6
// speedup vs baseline: 3.9689x; 1.2245x over previous
#include <cuda_runtime.h>
#include <cuda_bf16.h>
#include <cuda_fp16.h>
#include <cstdint>

#define Bq   8
#define Sq   1024
#define HIDq 1024
#define NHq  16
#define HDq  64
#define Mq   (Bq * Sq)   // 8192

// Scratch (device globals: allocation-free per harness rules)
__device__ __half g_xhi[(size_t)Mq * HIDq];    // A operand hi [M,K] (x, later ctx)
__device__ __half g_xlo[(size_t)Mq * HIDq];    // A operand lo
__device__ __half g_wth[(size_t)HIDq * HIDq];  // W^T fp16 [N,K]
__device__ __half g_qhi[(size_t)Bq * NHq * Sq * HDq];  // [B,NH,S,HD] (pre-scaled)
__device__ __half g_qlo[(size_t)Bq * NHq * Sq * HDq];
__device__ __half g_khi[(size_t)Bq * NHq * Sq * HDq];
__device__ __half g_vhi[(size_t)Bq * NHq * Sq * HDq];
__device__ __half g_vlo[(size_t)Bq * NHq * Sq * HDq];

// ===========================================================================
// PTX helpers (portable tensor ISA: ldmatrix + mma.sync, sm_80+)
// ===========================================================================
__device__ __forceinline__ uint32_t smem_to_u32(const void* p) {
    uint32_t a;
    asm("{ .reg .u64 t; cvta.to.shared.u64 t, %1; cvt.u32.u64 %0, t; }"
        : "=r"(a) : "l"(p));
    return a;
}

#define LDMX4(r, addr) \
    asm volatile("ldmatrix.sync.aligned.m8n8.x4.shared.b16 {%0,%1,%2,%3}, [%4];" \
        : "=r"((r)[0]), "=r"((r)[1]), "=r"((r)[2]), "=r"((r)[3]) : "r"(addr))

#define LDMX2(r, addr) \
    asm volatile("ldmatrix.sync.aligned.m8n8.x2.shared.b16 {%0,%1}, [%2];" \
        : "=r"((r)[0]), "=r"((r)[1]) : "r"(addr))

#define LDMX2T(r, addr) \
    asm volatile("ldmatrix.sync.aligned.m8n8.x2.trans.shared.b16 {%0,%1}, [%2];" \
        : "=r"((r)[0]), "=r"((r)[1]) : "r"(addr))

#define MMA_F16(d, a, b) \
    asm volatile("mma.sync.aligned.m16n8k16.row.col.f32.f16.f16.f32 " \
        "{%0,%1,%2,%3}, {%4,%5,%6,%7}, {%8,%9}, {%0,%1,%2,%3};" \
        : "+f"((d)[0]), "+f"((d)[1]), "+f"((d)[2]), "+f"((d)[3]) \
        : "r"((a)[0]), "r"((a)[1]), "r"((a)[2]), "r"((a)[3]), \
          "r"((b)[0]), "r"((b)[1]))

#define CP_ASYNC16(smem, gmem) \
    asm volatile("cp.async.cg.shared.global [%0], [%1], 16;" \
        :: "r"(smem), "l"(gmem) : "memory")
#define CP_COMMIT()  asm volatile("cp.async.commit_group;" ::: "memory")
#define CP_WAIT(n)   asm volatile("cp.async.wait_group %0;" :: "n"(n) : "memory")

// split f32 pair -> fp16x2 hi + fp16x2 lo
__device__ __forceinline__ void split2h(float a, float b, uint32_t& hi, uint32_t& lo) {
    __half2 h = __floats2half2_rn(a, b);
    float f0 = __half2float(__low2half(h));
    float f1 = __half2float(__high2half(h));
    __half2 l = __floats2half2_rn(a - f0, b - f1);
    hi = *(uint32_t*)&h;
    lo = *(uint32_t*)&l;
}

// ===========================================================================
// Conversion: x fp32 -> fp16 hi/lo split
// ===========================================================================
__global__ __launch_bounds__(256) void convert_x_kernel(const float* __restrict__ src)
{
    const size_t i = ((size_t)blockIdx.x * 256 + threadIdx.x) * 8;
    float4 v0 = *(const float4*)(src + i);
    float4 v1 = *(const float4*)(src + i + 4);
    float f[8] = {v0.x, v0.y, v0.z, v0.w, v1.x, v1.y, v1.z, v1.w};
    uint32_t hw[4], lw[4];
#pragma unroll
    for (int j = 0; j < 4; j++) split2h(f[2 * j], f[2 * j + 1], hw[j], lw[j]);
    *(uint4*)(g_xhi + i) = make_uint4(hw[0], hw[1], hw[2], hw[3]);
    *(uint4*)(g_xlo + i) = make_uint4(lw[0], lw[1], lw[2], lw[3]);
}

// ===========================================================================
// Weight transpose: g_wth[n][k] = fp16(W[k][n])
// ===========================================================================
__global__ __launch_bounds__(256) void convw_kernel(const float* __restrict__ W)
{
    __shared__ float tile[32][33];
    const int bx = blockIdx.x * 32, by = blockIdx.y * 32;
    const int tx = threadIdx.x & 31, ty = threadIdx.x >> 5;  // 32 x 8
#pragma unroll
    for (int i = 0; i < 4; i++)
        tile[ty + i * 8][tx] = W[(size_t)(by + ty + i * 8) * HIDq + bx + tx];
    __syncthreads();
#pragma unroll
    for (int i = 0; i < 4; i++)
        g_wth[(size_t)(bx + ty + i * 8) * HIDq + by + tx] =
            __float2half(tile[tx][ty + i * 8]);
}

// ===========================================================================
// 2-term fp16 mma.sync GEMM: C = (Xhi+Xlo)[8192,1024] @ Wh + bias
// MODE 0: fp16 hi/lo split, pre-scaled by rsqrt(HID), -> g_qhi/g_qlo
// MODE 1: fp16 single                              -> g_khi
// MODE 2: fp16 hi/lo split                         -> g_vhi/g_vlo
// MODE 3: fp32 row-major                           -> d_out
// ===========================================================================
#define KCH     32
#define TILEB   (128 * 40 * 2)          // 10240 B per tile (row stride 80 B)
#define GSMEM   (6 * TILEB)             // 61440 B (2 bufs x {Ahi, Alo, Bh})

template <int MODE>
__global__ __launch_bounds__(256, 2) void gemm_mma_kernel(
    const float* __restrict__ bias, float* __restrict__ Cout)
{
    extern __shared__ char sm[];
    const uint32_t sb = smem_to_u32(sm);

    const int tid = threadIdx.x, lane = tid & 31, wid = tid >> 5;
    const int wm = wid >> 2, wn = wid & 3;             // 2 x 4 warp grid
    const int bm = blockIdx.y * 128, bn = blockIdx.x * 128;

    float acc[4][4][4];
#pragma unroll
    for (int mi = 0; mi < 4; mi++)
#pragma unroll
        for (int ni = 0; ni < 4; ni++)
#pragma unroll
            for (int r = 0; r < 4; r++) acc[mi][ni][r] = 0.f;

    const int g0 = tid, g1 = tid + 256;
    const int r0g = g0 >> 2, s0 = g0 & 3;
    const int r1g = g1 >> 2, s1 = g1 & 3;

    auto issue = [&](int c) {
        const int p = c & 1;
        const uint32_t base = sb + (uint32_t)p * 3 * TILEB;
        const int k0 = c * KCH;
        const uint32_t so0 = (uint32_t)r0g * 80 + (uint32_t)s0 * 16;
        const uint32_t so1 = (uint32_t)r1g * 80 + (uint32_t)s1 * 16;
        const size_t ga0 = (size_t)(bm + r0g) * HIDq + k0 + s0 * 8;
        const size_t ga1 = (size_t)(bm + r1g) * HIDq + k0 + s1 * 8;
        const size_t gb0 = (size_t)(bn + r0g) * HIDq + k0 + s0 * 8;
        const size_t gb1 = (size_t)(bn + r1g) * HIDq + k0 + s1 * 8;
        CP_ASYNC16(base + so0,             g_xhi + ga0);
        CP_ASYNC16(base + so1,             g_xhi + ga1);
        CP_ASYNC16(base + TILEB + so0,     g_xlo + ga0);
        CP_ASYNC16(base + TILEB + so1,     g_xlo + ga1);
        CP_ASYNC16(base + 2 * TILEB + so0, g_wth + gb0);
        CP_ASYNC16(base + 2 * TILEB + so1, g_wth + gb1);
        CP_COMMIT();
    };

    issue(0);

    for (int c = 0; c < HIDq / KCH; c++) {
        if (c + 1 < HIDq / KCH) { issue(c + 1); CP_WAIT(1); }
        else                    { CP_WAIT(0); }
        __syncthreads();

        const uint32_t base = sb + (uint32_t)(c & 1) * 3 * TILEB;

#pragma unroll
        for (int kk = 0; kk < KCH; kk += 16) {
            uint32_t bh[4][2];
#pragma unroll
            for (int ni = 0; ni < 4; ni++) {
                const uint32_t baddr = base + 2 * TILEB
                    + (uint32_t)(wn * 32 + ni * 8 + (lane & 7)) * 80
                    + (uint32_t)(kk + ((lane >> 3) & 1) * 8) * 2;
                LDMX2(bh[ni], baddr);
            }
#pragma unroll
            for (int mi = 0; mi < 4; mi++) {
                const uint32_t aaddr = base
                    + (uint32_t)(wm * 64 + mi * 16 + (lane & 15)) * 80
                    + (uint32_t)(kk + (lane >> 4) * 8) * 2;
                uint32_t ah[4], al[4];
                LDMX4(ah, aaddr);
                LDMX4(al, aaddr + TILEB);
#pragma unroll
                for (int ni = 0; ni < 4; ni++) {
                    MMA_F16(acc[mi][ni], ah, bh[ni]);
                    MMA_F16(acc[mi][ni], al, bh[ni]);
                }
            }
        }
        __syncthreads();
    }

    const int rbase = bm + wm * 64 + (lane >> 2);
    const int cbase = bn + wn * 32 + (lane & 3) * 2;
#pragma unroll
    for (int mi = 0; mi < 4; mi++) {
#pragma unroll
        for (int ni = 0; ni < 4; ni++) {
            const int col = cbase + ni * 8;
            const float2 b2 = *(const float2*)(bias + col);
#pragma unroll
            for (int half = 0; half < 2; half++) {
                const int row = rbase + mi * 16 + half * 8;
                float ox = acc[mi][ni][half * 2 + 0] + b2.x;
                float oy = acc[mi][ni][half * 2 + 1] + b2.y;
                if (MODE == 3) {
                    *(float2*)(Cout + (size_t)row * HIDq + col) = make_float2(ox, oy);
                } else {
                    const int b = row >> 10, s = row & 1023;
                    const int h = col >> 6,  d = col & 63;
                    const size_t off = (((size_t)(b * NHq + h)) * Sq + s) * HDq + d;
                    if (MODE == 0) {
                        uint32_t hi, lo;
                        split2h(ox * 0.03125f, oy * 0.03125f, hi, lo);
                        *(uint32_t*)(g_qhi + off) = hi;
                        *(uint32_t*)(g_qlo + off) = lo;
                    } else if (MODE == 1) {
                        __half2 h2 = __floats2half2_rn(ox, oy);
                        *(uint32_t*)(g_khi + off) = *(uint32_t*)&h2;
                    } else {
                        uint32_t hi, lo;
                        split2h(ox, oy, hi, lo);
                        *(uint32_t*)(g_vhi + off) = hi;
                        *(uint32_t*)(g_vlo + off) = lo;
                    }
                }
            }
        }
    }
}

// ===========================================================================
// fp16 flash attention: per (b,h), 128-query tile, 64-key stages (2-stage).
// 256 threads = 8 warps, warp owns 16 query rows.
// Scores: (Qhi+Qlo)*Khi (2 MMA); PV: P_fp16*(Vhi+Vlo) (2 MMA).
// ctx -> fp16 hi/lo into g_xhi/g_xlo [B*S, HID].
// ===========================================================================
#define QTILE  18432                    // 128 rows x 144 B
#define KVTILE 9216                     // 64 rows x 144 B
#define KVSTG  (3 * KVTILE)             // Khi, Vhi, Vlo
#define KVOFF  (2 * QTILE)
#define ASMEM  (KVOFF + 2 * KVSTG)      // 92160
#define NTK    (Sq / 64)                // 16

__global__ __launch_bounds__(256, 2) void attn_mma_kernel(const float* __restrict__ mask)
{
    extern __shared__ char sm[];
    const uint32_t sb = smem_to_u32(sm);

    const int bh = blockIdx.y;
    const int b = bh >> 4, h = bh & 15;
    const int qbase = blockIdx.x * 128;
    const int tid = threadIdx.x, lane = tid & 31, wid = tid >> 5;
    const int wrow = wid * 16;

    const size_t hb = (size_t)bh * Sq * HDq;
    const __half* Qhi = g_qhi + hb;
    const __half* Qlo = g_qlo + hb;
    const __half* KVg[3] = {g_khi + hb, g_vhi + hb, g_vlo + hb};

    // Q load (joins cp.async group 0 with KV stage 0)
#pragma unroll
    for (int t = 0; t < 8; t++) {
        const int which = t >> 2;               // 0 = hi, 1 = lo
        const int id = (t & 3) * 256 + tid;
        const int row = id >> 3, seg = id & 7;
        const __half* src = (which ? Qlo : Qhi) + (size_t)(qbase + row) * HDq + seg * 8;
        CP_ASYNC16(sb + (uint32_t)which * QTILE + (uint32_t)row * 144 + seg * 16, src);
    }

    auto issue_kv = [&](int kt) {
        const uint32_t base = sb + KVOFF + (uint32_t)(kt & 1) * KVSTG;
#pragma unroll
        for (int t = 0; t < 6; t++) {
            const int which = t >> 1;           // 0=Khi, 1=Vhi, 2=Vlo
            const int id = (t & 1) * 256 + tid;
            const int row = id >> 3, seg = id & 7;
            CP_ASYNC16(base + (uint32_t)which * KVTILE + (uint32_t)row * 144 + seg * 16,
                       KVg[which] + (size_t)(kt * 64 + row) * HDq + seg * 8);
        }
        CP_COMMIT();
    };

    issue_kv(0);

    float m_st[2] = {-1e30f, -1e30f};
    float l_st[2] = {0.f, 0.f};
    float ctx[8][4];
#pragma unroll
    for (int n = 0; n < 8; n++)
#pragma unroll
        for (int r = 0; r < 4; r++) ctx[n][r] = 0.f;

    const int r0 = qbase + wrow + (lane >> 2);

    for (int kt = 0; kt < NTK; kt++) {
        if (kt + 1 < NTK) { issue_kv(kt + 1); CP_WAIT(1); }
        else              { CP_WAIT(0); }
        __syncthreads();

        const uint32_t kvb = sb + KVOFF + (uint32_t)(kt & 1) * KVSTG;

        // ---- scores S = (Qhi+Qlo) Khi^T ----
        float accs[8][4];
#pragma unroll
        for (int n = 0; n < 8; n++)
#pragma unroll
            for (int r = 0; r < 4; r++) accs[n][r] = 0.f;

#pragma unroll
        for (int k0 = 0; k0 < 64; k0 += 16) {
            uint32_t ah[4], al[4];
            const uint32_t aaddr = sb + (uint32_t)(wrow + (lane & 15)) * 144
                                 + (uint32_t)(k0 + (lane >> 4) * 8) * 2;
            LDMX4(ah, aaddr);
            LDMX4(al, aaddr + QTILE);
#pragma unroll
            for (int n = 0; n < 8; n++) {
                const uint32_t baddr = kvb + (uint32_t)(n * 8 + (lane & 7)) * 144
                                     + (uint32_t)(k0 + ((lane >> 3) & 1) * 8) * 2;
                uint32_t kb[2];
                LDMX2(kb, baddr);
                MMA_F16(accs[n], ah, kb);
                MMA_F16(accs[n], al, kb);
            }
        }

        // ---- mask (scale already folded into Q) ----
        const float* mrow0 = mask + ((size_t)b * Sq + r0) * Sq + kt * 64 + (lane & 3) * 2;
        const float* mrow1 = mrow0 + 8 * Sq;
#pragma unroll
        for (int n = 0; n < 8; n++) {
            const float2 m0 = *(const float2*)(mrow0 + n * 8);
            const float2 m1 = *(const float2*)(mrow1 + n * 8);
            accs[n][0] = fmaf(m0.x, -1e9f, accs[n][0]);
            accs[n][1] = fmaf(m0.y, -1e9f, accs[n][1]);
            accs[n][2] = fmaf(m1.x, -1e9f, accs[n][2]);
            accs[n][3] = fmaf(m1.y, -1e9f, accs[n][3]);
        }

        // ---- online softmax (rows r0, r0+8) ----
        float mx0 = -1e30f, mx1 = -1e30f;
#pragma unroll
        for (int n = 0; n < 8; n++) {
            mx0 = fmaxf(mx0, fmaxf(accs[n][0], accs[n][1]));
            mx1 = fmaxf(mx1, fmaxf(accs[n][2], accs[n][3]));
        }
        mx0 = fmaxf(mx0, __shfl_xor_sync(0xffffffffu, mx0, 1));
        mx0 = fmaxf(mx0, __shfl_xor_sync(0xffffffffu, mx0, 2));
        mx1 = fmaxf(mx1, __shfl_xor_sync(0xffffffffu, mx1, 1));
        mx1 = fmaxf(mx1, __shfl_xor_sync(0xffffffffu, mx1, 2));

        const float mn0 = fmaxf(m_st[0], mx0);
        const float mn1 = fmaxf(m_st[1], mx1);
        const float al0 = __expf(m_st[0] - mn0);
        const float al1 = __expf(m_st[1] - mn1);
        m_st[0] = mn0; m_st[1] = mn1;

        float sum0 = 0.f, sum1 = 0.f;
#pragma unroll
        for (int n = 0; n < 8; n++) {
            accs[n][0] = __expf(accs[n][0] - mn0);
            accs[n][1] = __expf(accs[n][1] - mn0);
            accs[n][2] = __expf(accs[n][2] - mn1);
            accs[n][3] = __expf(accs[n][3] - mn1);
            sum0 += accs[n][0] + accs[n][1];
            sum1 += accs[n][2] + accs[n][3];
        }
        sum0 += __shfl_xor_sync(0xffffffffu, sum0, 1);
        sum0 += __shfl_xor_sync(0xffffffffu, sum0, 2);
        sum1 += __shfl_xor_sync(0xffffffffu, sum1, 1);
        sum1 += __shfl_xor_sync(0xffffffffu, sum1, 2);
        l_st[0] = l_st[0] * al0 + sum0;
        l_st[1] = l_st[1] * al1 + sum1;

#pragma unroll
        for (int n = 0; n < 8; n++) {
            ctx[n][0] *= al0; ctx[n][1] *= al0;
            ctx[n][2] *= al1; ctx[n][3] *= al1;
        }

        // ---- PV: ctx += P_fp16 (Vhi + Vlo) ----
        const uint32_t vbase = kvb + KVTILE;
#pragma unroll
        for (int kk2 = 0; kk2 < 4; kk2++) {
            uint32_t pf[4];
            __half2 p0 = __floats2half2_rn(accs[2 * kk2][0],     accs[2 * kk2][1]);
            __half2 p1 = __floats2half2_rn(accs[2 * kk2][2],     accs[2 * kk2][3]);
            __half2 p2 = __floats2half2_rn(accs[2 * kk2 + 1][0], accs[2 * kk2 + 1][1]);
            __half2 p3 = __floats2half2_rn(accs[2 * kk2 + 1][2], accs[2 * kk2 + 1][3]);
            pf[0] = *(uint32_t*)&p0; pf[1] = *(uint32_t*)&p1;
            pf[2] = *(uint32_t*)&p2; pf[3] = *(uint32_t*)&p3;
#pragma unroll
            for (int n = 0; n < 8; n++) {
                const uint32_t vaddr = vbase + (uint32_t)(kk2 * 16 + (lane & 15)) * 144
                                     + (uint32_t)n * 16;
                uint32_t vh[2], vl[2];
                LDMX2T(vh, vaddr);
                LDMX2T(vl, vaddr + KVTILE);
                MMA_F16(ctx[n], pf, vh);
                MMA_F16(ctx[n], pf, vl);
            }
        }
        __syncthreads();
    }

    // ---- epilogue: ctx / l -> fp16 hi/lo into g_xhi/g_xlo [B*S, HID] ----
    const float inv0 = 1.0f / l_st[0];
    const float inv1 = 1.0f / l_st[1];
    const int cb = h * HDq + (lane & 3) * 2;
#pragma unroll
    for (int n = 0; n < 8; n++) {
        const int col = cb + n * 8;
        const size_t off0 = ((size_t)(b * Sq + r0)) * HIDq + col;
        const size_t off1 = ((size_t)(b * Sq + r0 + 8)) * HIDq + col;
        uint32_t hi, lo;
        split2h(ctx[n][0] * inv0, ctx[n][1] * inv0, hi, lo);
        *(uint32_t*)(g_xhi + off0) = hi;
        *(uint32_t*)(g_xlo + off0) = lo;
        split2h(ctx[n][2] * inv1, ctx[n][3] * inv1, hi, lo);
        *(uint32_t*)(g_xhi + off1) = hi;
        *(uint32_t*)(g_xlo + off1) = lo;
    }
}

// ---------------------------------------------------------------------------
extern "C" void kernel_launch(void* const* d_in, const int* in_sizes, int n_in,
                              void* d_out, int out_size)
{
    (void)in_sizes; (void)n_in; (void)out_size;
    const float* x   = (const float*)d_in[0];
    const float* msk = (const float*)d_in[1];
    const float* Wq  = (const float*)d_in[2];
    const float* bq  = (const float*)d_in[3];
    const float* Wk  = (const float*)d_in[4];
    const float* bk  = (const float*)d_in[5];
    const float* Wv  = (const float*)d_in[6];
    const float* bv  = (const float*)d_in[7];
    const float* Wp  = (const float*)d_in[8];
    const float* bp  = (const float*)d_in[9];
    float* out = (float*)d_out;

    cudaFuncSetAttribute(gemm_mma_kernel<0>, cudaFuncAttributeMaxDynamicSharedMemorySize, GSMEM);
    cudaFuncSetAttribute(gemm_mma_kernel<1>, cudaFuncAttributeMaxDynamicSharedMemorySize, GSMEM);
    cudaFuncSetAttribute(gemm_mma_kernel<2>, cudaFuncAttributeMaxDynamicSharedMemorySize, GSMEM);
    cudaFuncSetAttribute(gemm_mma_kernel<3>, cudaFuncAttributeMaxDynamicSharedMemorySize, GSMEM);
    cudaFuncSetAttribute(attn_mma_kernel, cudaFuncAttributeMaxDynamicSharedMemorySize, ASMEM);

    const dim3 cw(32, 32);
    const dim3 gg(HIDq / 128, Mq / 128);   // 8 x 64

    convert_x_kernel<<<(Mq * HIDq) / (256 * 8), 256>>>(x);

    convw_kernel<<<cw, 256>>>(Wq);
    gemm_mma_kernel<0><<<gg, 256, GSMEM>>>(bq, nullptr);
    convw_kernel<<<cw, 256>>>(Wk);
    gemm_mma_kernel<1><<<gg, 256, GSMEM>>>(bk, nullptr);
    convw_kernel<<<cw, 256>>>(Wv);
    gemm_mma_kernel<2><<<gg, 256, GSMEM>>>(bv, nullptr);

    attn_mma_kernel<<<dim3(Sq / 128, Bq * NHq), 256, ASMEM>>>(msk);

    convw_kernel<<<cw, 256>>>(Wp);
    gemm_mma_kernel<3><<<gg, 256, GSMEM>>>(bp, out);
}

// round 8
// speedup vs baseline: 4.4260x; 1.1152x over previous
#include <cuda_runtime.h>
#include <cuda_fp16.h>
#include <cstdint>

#define Bq   8
#define Sq   1024
#define HIDq 1024
#define NHq  16
#define HDq  64
#define Mq   (Bq * Sq)   // 8192

// Scratch (device globals: allocation-free per harness rules)
__device__ __half g_xhi[(size_t)Mq * HIDq];    // A operand hi [M,K] (x, later ctx)
__device__ __half g_xlo[(size_t)Mq * HIDq];    // A operand lo
__device__ __half g_wt4[(size_t)4 * HIDq * HIDq];  // W^T fp16 [4][N,K] (q,k,v,p)
__device__ __half g_qh[(size_t)Bq * NHq * Sq * HDq];  // [B,NH,S,HD] (pre-scaled)
__device__ __half g_kh[(size_t)Bq * NHq * Sq * HDq];
__device__ __half g_vh[(size_t)Bq * NHq * Sq * HDq];

// ===========================================================================
// PTX helpers (portable tensor ISA: ldmatrix + mma.sync, sm_80+)
// ===========================================================================
__device__ __forceinline__ uint32_t smem_to_u32(const void* p) {
    uint32_t a;
    asm("{ .reg .u64 t; cvta.to.shared.u64 t, %1; cvt.u32.u64 %0, t; }"
        : "=r"(a) : "l"(p));
    return a;
}

#define LDMX4(r, addr) \
    asm volatile("ldmatrix.sync.aligned.m8n8.x4.shared.b16 {%0,%1,%2,%3}, [%4];" \
        : "=r"((r)[0]), "=r"((r)[1]), "=r"((r)[2]), "=r"((r)[3]) : "r"(addr))

#define LDMX2(r, addr) \
    asm volatile("ldmatrix.sync.aligned.m8n8.x2.shared.b16 {%0,%1}, [%2];" \
        : "=r"((r)[0]), "=r"((r)[1]) : "r"(addr))

#define LDMX2T(r, addr) \
    asm volatile("ldmatrix.sync.aligned.m8n8.x2.trans.shared.b16 {%0,%1}, [%2];" \
        : "=r"((r)[0]), "=r"((r)[1]) : "r"(addr))

#define MMA_F16(d, a, b) \
    asm volatile("mma.sync.aligned.m16n8k16.row.col.f32.f16.f16.f32 " \
        "{%0,%1,%2,%3}, {%4,%5,%6,%7}, {%8,%9}, {%0,%1,%2,%3};" \
        : "+f"((d)[0]), "+f"((d)[1]), "+f"((d)[2]), "+f"((d)[3]) \
        : "r"((a)[0]), "r"((a)[1]), "r"((a)[2]), "r"((a)[3]), \
          "r"((b)[0]), "r"((b)[1]))

#define CP_ASYNC16(smem, gmem) \
    asm volatile("cp.async.cg.shared.global [%0], [%1], 16;" \
        :: "r"(smem), "l"(gmem) : "memory")
#define CP_COMMIT()  asm volatile("cp.async.commit_group;" ::: "memory")
#define CP_WAIT(n)   asm volatile("cp.async.wait_group %0;" :: "n"(n) : "memory")

// split f32 pair -> fp16x2 hi + fp16x2 lo
__device__ __forceinline__ void split2h(float a, float b, uint32_t& hi, uint32_t& lo) {
    __half2 h = __floats2half2_rn(a, b);
    float f0 = __half2float(__low2half(h));
    float f1 = __half2float(__high2half(h));
    __half2 l = __floats2half2_rn(a - f0, b - f1);
    hi = *(uint32_t*)&h;
    lo = *(uint32_t*)&l;
}

// ===========================================================================
// Conversion: x fp32 -> fp16 hi/lo split
// ===========================================================================
__global__ __launch_bounds__(256) void convert_x_kernel(const float* __restrict__ src)
{
    const size_t i = ((size_t)blockIdx.x * 256 + threadIdx.x) * 8;
    float4 v0 = *(const float4*)(src + i);
    float4 v1 = *(const float4*)(src + i + 4);
    float f[8] = {v0.x, v0.y, v0.z, v0.w, v1.x, v1.y, v1.z, v1.w};
    uint32_t hw[4], lw[4];
#pragma unroll
    for (int j = 0; j < 4; j++) split2h(f[2 * j], f[2 * j + 1], hw[j], lw[j]);
    *(uint4*)(g_xhi + i) = make_uint4(hw[0], hw[1], hw[2], hw[3]);
    *(uint4*)(g_xlo + i) = make_uint4(lw[0], lw[1], lw[2], lw[3]);
}

// ===========================================================================
// All-weights transpose: g_wt4[z][n][k] = fp16(Wz[k][n]) for z in {q,k,v,p}
// ===========================================================================
__global__ __launch_bounds__(256) void convw_all_kernel(
    const float* __restrict__ W0, const float* __restrict__ W1,
    const float* __restrict__ W2, const float* __restrict__ W3)
{
    __shared__ float tile[32][33];
    const float* W = (blockIdx.z == 0) ? W0 : (blockIdx.z == 1) ? W1
                   : (blockIdx.z == 2) ? W2 : W3;
    __half* dst = g_wt4 + (size_t)blockIdx.z * HIDq * HIDq;
    const int bx = blockIdx.x * 32, by = blockIdx.y * 32;
    const int tx = threadIdx.x & 31, ty = threadIdx.x >> 5;  // 32 x 8
#pragma unroll
    for (int i = 0; i < 4; i++)
        tile[ty + i * 8][tx] = W[(size_t)(by + ty + i * 8) * HIDq + bx + tx];
    __syncthreads();
#pragma unroll
    for (int i = 0; i < 4; i++)
        dst[(size_t)(bx + ty + i * 8) * HIDq + by + tx] =
            __float2half(tile[tx][ty + i * 8]);
}

// ===========================================================================
// 2-term fp16 mma.sync GEMM: C = (Xhi+Xlo)[8192,1024] @ g_wt4[MODE] + bias
// (weight slot selected by MODE INSIDE the kernel — device symbol must not
//  be referenced from host code)
// MODE 0: fp16, pre-scaled by rsqrt(HID) -> g_qh   [B,NH,S,HD]
// MODE 1: fp16                           -> g_kh
// MODE 2: fp16                           -> g_vh
// MODE 3: fp32 row-major                 -> d_out
// ===========================================================================
#define KCH     32
#define TILEB   (128 * 40 * 2)          // 10240 B per tile (row stride 80 B)
#define GSMEM   (6 * TILEB)             // 61440 B (2 bufs x {Ahi, Alo, Bh})

template <int MODE>
__global__ __launch_bounds__(256, 2) void gemm_mma_kernel(
    const float* __restrict__ bias, float* __restrict__ Cout)
{
    extern __shared__ char sm[];
    const uint32_t sb = smem_to_u32(sm);
    const __half* Wt = g_wt4 + (size_t)MODE * HIDq * HIDq;

    const int tid = threadIdx.x, lane = tid & 31, wid = tid >> 5;
    const int wm = wid >> 2, wn = wid & 3;             // 2 x 4 warp grid
    const int bm = blockIdx.y * 128, bn = blockIdx.x * 128;

    float acc[4][4][4];
#pragma unroll
    for (int mi = 0; mi < 4; mi++)
#pragma unroll
        for (int ni = 0; ni < 4; ni++)
#pragma unroll
            for (int r = 0; r < 4; r++) acc[mi][ni][r] = 0.f;

    const int g0 = tid, g1 = tid + 256;
    const int r0g = g0 >> 2, s0 = g0 & 3;
    const int r1g = g1 >> 2, s1 = g1 & 3;

    auto issue = [&](int c) {
        const int p = c & 1;
        const uint32_t base = sb + (uint32_t)p * 3 * TILEB;
        const int k0 = c * KCH;
        const uint32_t so0 = (uint32_t)r0g * 80 + (uint32_t)s0 * 16;
        const uint32_t so1 = (uint32_t)r1g * 80 + (uint32_t)s1 * 16;
        const size_t ga0 = (size_t)(bm + r0g) * HIDq + k0 + s0 * 8;
        const size_t ga1 = (size_t)(bm + r1g) * HIDq + k0 + s1 * 8;
        const size_t gb0 = (size_t)(bn + r0g) * HIDq + k0 + s0 * 8;
        const size_t gb1 = (size_t)(bn + r1g) * HIDq + k0 + s1 * 8;
        CP_ASYNC16(base + so0,             g_xhi + ga0);
        CP_ASYNC16(base + so1,             g_xhi + ga1);
        CP_ASYNC16(base + TILEB + so0,     g_xlo + ga0);
        CP_ASYNC16(base + TILEB + so1,     g_xlo + ga1);
        CP_ASYNC16(base + 2 * TILEB + so0, Wt + gb0);
        CP_ASYNC16(base + 2 * TILEB + so1, Wt + gb1);
        CP_COMMIT();
    };

    issue(0);

    for (int c = 0; c < HIDq / KCH; c++) {
        if (c + 1 < HIDq / KCH) { issue(c + 1); CP_WAIT(1); }
        else                    { CP_WAIT(0); }
        __syncthreads();

        const uint32_t base = sb + (uint32_t)(c & 1) * 3 * TILEB;

#pragma unroll
        for (int kk = 0; kk < KCH; kk += 16) {
            uint32_t bh[4][2];
#pragma unroll
            for (int ni = 0; ni < 4; ni++) {
                const uint32_t baddr = base + 2 * TILEB
                    + (uint32_t)(wn * 32 + ni * 8 + (lane & 7)) * 80
                    + (uint32_t)(kk + ((lane >> 3) & 1) * 8) * 2;
                LDMX2(bh[ni], baddr);
            }
#pragma unroll
            for (int mi = 0; mi < 4; mi++) {
                const uint32_t aaddr = base
                    + (uint32_t)(wm * 64 + mi * 16 + (lane & 15)) * 80
                    + (uint32_t)(kk + (lane >> 4) * 8) * 2;
                uint32_t ah[4], al[4];
                LDMX4(ah, aaddr);
                LDMX4(al, aaddr + TILEB);
#pragma unroll
                for (int ni = 0; ni < 4; ni++) {
                    MMA_F16(acc[mi][ni], ah, bh[ni]);
                    MMA_F16(acc[mi][ni], al, bh[ni]);
                }
            }
        }
        __syncthreads();
    }

    const int rbase = bm + wm * 64 + (lane >> 2);
    const int cbase = bn + wn * 32 + (lane & 3) * 2;
#pragma unroll
    for (int mi = 0; mi < 4; mi++) {
#pragma unroll
        for (int ni = 0; ni < 4; ni++) {
            const int col = cbase + ni * 8;
            const float2 b2 = *(const float2*)(bias + col);
#pragma unroll
            for (int half = 0; half < 2; half++) {
                const int row = rbase + mi * 16 + half * 8;
                float ox = acc[mi][ni][half * 2 + 0] + b2.x;
                float oy = acc[mi][ni][half * 2 + 1] + b2.y;
                if (MODE == 3) {
                    *(float2*)(Cout + (size_t)row * HIDq + col) = make_float2(ox, oy);
                } else {
                    const int b = row >> 10, s = row & 1023;
                    const int h = col >> 6,  d = col & 63;
                    const size_t off = (((size_t)(b * NHq + h)) * Sq + s) * HDq + d;
                    if (MODE == 0) { ox *= 0.03125f; oy *= 0.03125f; }
                    __half2 h2 = __floats2half2_rn(ox, oy);
                    __half* dst = (MODE == 0) ? g_qh : (MODE == 1) ? g_kh : g_vh;
                    *(uint32_t*)(dst + off) = *(uint32_t*)&h2;
                }
            }
        }
    }
}

// ===========================================================================
// fp16 flash attention: per (b,h), 128-query tile, 64-key stages (2-stage).
// 256 threads = 8 warps, warp owns 16 query rows.
// Scores: Q*K (1 MMA); PV: P*V (1 MMA). smem 55 KB.
// ctx -> fp16 hi/lo into g_xhi/g_xlo [B*S, HID].
// ===========================================================================
#define QTILE  18432                    // 128 rows x 144 B
#define KVTILE 9216                     // 64 rows x 144 B
#define KVSTG  (2 * KVTILE)             // Kh, Vh
#define KVOFF  QTILE
#define ASMEM  (KVOFF + 2 * KVSTG)      // 55296
#define NTK    (Sq / 64)                // 16

__global__ __launch_bounds__(256, 2) void attn_mma_kernel(const float* __restrict__ mask)
{
    extern __shared__ char sm[];
    const uint32_t sb = smem_to_u32(sm);

    const int bh = blockIdx.y;
    const int b = bh >> 4, h = bh & 15;
    const int qbase = blockIdx.x * 128;
    const int tid = threadIdx.x, lane = tid & 31, wid = tid >> 5;
    const int wrow = wid * 16;

    const size_t hb = (size_t)bh * Sq * HDq;
    const __half* Qg = g_qh + hb;
    const __half* KVg[2] = {g_kh + hb, g_vh + hb};

    // Q load (joins cp.async group 0 with KV stage 0)
#pragma unroll
    for (int t = 0; t < 4; t++) {
        const int id = t * 256 + tid;
        const int row = id >> 3, seg = id & 7;
        CP_ASYNC16(sb + (uint32_t)row * 144 + seg * 16,
                   Qg + (size_t)(qbase + row) * HDq + seg * 8);
    }

    auto issue_kv = [&](int kt) {
        const uint32_t base = sb + KVOFF + (uint32_t)(kt & 1) * KVSTG;
#pragma unroll
        for (int t = 0; t < 4; t++) {
            const int which = t >> 1;           // 0=Kh, 1=Vh
            const int id = (t & 1) * 256 + tid;
            const int row = id >> 3, seg = id & 7;
            CP_ASYNC16(base + (uint32_t)which * KVTILE + (uint32_t)row * 144 + seg * 16,
                       KVg[which] + (size_t)(kt * 64 + row) * HDq + seg * 8);
        }
        CP_COMMIT();
    };

    issue_kv(0);

    float m_st[2] = {-1e30f, -1e30f};
    float l_st[2] = {0.f, 0.f};
    float ctx[8][4];
#pragma unroll
    for (int n = 0; n < 8; n++)
#pragma unroll
        for (int r = 0; r < 4; r++) ctx[n][r] = 0.f;

    const int r0 = qbase + wrow + (lane >> 2);

    for (int kt = 0; kt < NTK; kt++) {
        if (kt + 1 < NTK) { issue_kv(kt + 1); CP_WAIT(1); }
        else              { CP_WAIT(0); }
        __syncthreads();

        const uint32_t kvb = sb + KVOFF + (uint32_t)(kt & 1) * KVSTG;

        // ---- scores S = Q K^T ----
        float accs[8][4];
#pragma unroll
        for (int n = 0; n < 8; n++)
#pragma unroll
            for (int r = 0; r < 4; r++) accs[n][r] = 0.f;

#pragma unroll
        for (int k0 = 0; k0 < 64; k0 += 16) {
            uint32_t ah[4];
            const uint32_t aaddr = sb + (uint32_t)(wrow + (lane & 15)) * 144
                                 + (uint32_t)(k0 + (lane >> 4) * 8) * 2;
            LDMX4(ah, aaddr);
#pragma unroll
            for (int n = 0; n < 8; n++) {
                const uint32_t baddr = kvb + (uint32_t)(n * 8 + (lane & 7)) * 144
                                     + (uint32_t)(k0 + ((lane >> 3) & 1) * 8) * 2;
                uint32_t kb[2];
                LDMX2(kb, baddr);
                MMA_F16(accs[n], ah, kb);
            }
        }

        // ---- mask (scale already folded into Q) ----
        const float* mrow0 = mask + ((size_t)b * Sq + r0) * Sq + kt * 64 + (lane & 3) * 2;
        const float* mrow1 = mrow0 + 8 * Sq;
#pragma unroll
        for (int n = 0; n < 8; n++) {
            const float2 m0 = *(const float2*)(mrow0 + n * 8);
            const float2 m1 = *(const float2*)(mrow1 + n * 8);
            accs[n][0] = fmaf(m0.x, -1e9f, accs[n][0]);
            accs[n][1] = fmaf(m0.y, -1e9f, accs[n][1]);
            accs[n][2] = fmaf(m1.x, -1e9f, accs[n][2]);
            accs[n][3] = fmaf(m1.y, -1e9f, accs[n][3]);
        }

        // ---- online softmax (rows r0, r0+8) ----
        float mx0 = -1e30f, mx1 = -1e30f;
#pragma unroll
        for (int n = 0; n < 8; n++) {
            mx0 = fmaxf(mx0, fmaxf(accs[n][0], accs[n][1]));
            mx1 = fmaxf(mx1, fmaxf(accs[n][2], accs[n][3]));
        }
        mx0 = fmaxf(mx0, __shfl_xor_sync(0xffffffffu, mx0, 1));
        mx0 = fmaxf(mx0, __shfl_xor_sync(0xffffffffu, mx0, 2));
        mx1 = fmaxf(mx1, __shfl_xor_sync(0xffffffffu, mx1, 1));
        mx1 = fmaxf(mx1, __shfl_xor_sync(0xffffffffu, mx1, 2));

        const float mn0 = fmaxf(m_st[0], mx0);
        const float mn1 = fmaxf(m_st[1], mx1);
        const float al0 = __expf(m_st[0] - mn0);
        const float al1 = __expf(m_st[1] - mn1);
        m_st[0] = mn0; m_st[1] = mn1;

        float sum0 = 0.f, sum1 = 0.f;
#pragma unroll
        for (int n = 0; n < 8; n++) {
            accs[n][0] = __expf(accs[n][0] - mn0);
            accs[n][1] = __expf(accs[n][1] - mn0);
            accs[n][2] = __expf(accs[n][2] - mn1);
            accs[n][3] = __expf(accs[n][3] - mn1);
            sum0 += accs[n][0] + accs[n][1];
            sum1 += accs[n][2] + accs[n][3];
        }
        sum0 += __shfl_xor_sync(0xffffffffu, sum0, 1);
        sum0 += __shfl_xor_sync(0xffffffffu, sum0, 2);
        sum1 += __shfl_xor_sync(0xffffffffu, sum1, 1);
        sum1 += __shfl_xor_sync(0xffffffffu, sum1, 2);
        l_st[0] = l_st[0] * al0 + sum0;
        l_st[1] = l_st[1] * al1 + sum1;

#pragma unroll
        for (int n = 0; n < 8; n++) {
            ctx[n][0] *= al0; ctx[n][1] *= al0;
            ctx[n][2] *= al1; ctx[n][3] *= al1;
        }

        // ---- PV: ctx += P_fp16 V ----
        const uint32_t vbase = kvb + KVTILE;
#pragma unroll
        for (int kk2 = 0; kk2 < 4; kk2++) {
            uint32_t pf[4];
            __half2 p0 = __floats2half2_rn(accs[2 * kk2][0],     accs[2 * kk2][1]);
            __half2 p1 = __floats2half2_rn(accs[2 * kk2][2],     accs[2 * kk2][3]);
            __half2 p2 = __floats2half2_rn(accs[2 * kk2 + 1][0], accs[2 * kk2 + 1][1]);
            __half2 p3 = __floats2half2_rn(accs[2 * kk2 + 1][2], accs[2 * kk2 + 1][3]);
            pf[0] = *(uint32_t*)&p0; pf[1] = *(uint32_t*)&p1;
            pf[2] = *(uint32_t*)&p2; pf[3] = *(uint32_t*)&p3;
#pragma unroll
            for (int n = 0; n < 8; n++) {
                const uint32_t vaddr = vbase + (uint32_t)(kk2 * 16 + (lane & 15)) * 144
                                     + (uint32_t)n * 16;
                uint32_t vh[2];
                LDMX2T(vh, vaddr);
                MMA_F16(ctx[n], pf, vh);
            }
        }
        __syncthreads();
    }

    // ---- epilogue: ctx / l -> fp16 hi/lo into g_xhi/g_xlo [B*S, HID] ----
    const float inv0 = 1.0f / l_st[0];
    const float inv1 = 1.0f / l_st[1];
    const int cb = h * HDq + (lane & 3) * 2;
#pragma unroll
    for (int n = 0; n < 8; n++) {
        const int col = cb + n * 8;
        const size_t off0 = ((size_t)(b * Sq + r0)) * HIDq + col;
        const size_t off1 = ((size_t)(b * Sq + r0 + 8)) * HIDq + col;
        uint32_t hi, lo;
        split2h(ctx[n][0] * inv0, ctx[n][1] * inv0, hi, lo);
        *(uint32_t*)(g_xhi + off0) = hi;
        *(uint32_t*)(g_xlo + off0) = lo;
        split2h(ctx[n][2] * inv1, ctx[n][3] * inv1, hi, lo);
        *(uint32_t*)(g_xhi + off1) = hi;
        *(uint32_t*)(g_xlo + off1) = lo;
    }
}

// ---------------------------------------------------------------------------
extern "C" void kernel_launch(void* const* d_in, const int* in_sizes, int n_in,
                              void* d_out, int out_size)
{
    (void)in_sizes; (void)n_in; (void)out_size;
    const float* x   = (const float*)d_in[0];
    const float* msk = (const float*)d_in[1];
    const float* Wq  = (const float*)d_in[2];
    const float* bq  = (const float*)d_in[3];
    const float* Wk  = (const float*)d_in[4];
    const float* bk  = (const float*)d_in[5];
    const float* Wv  = (const float*)d_in[6];
    const float* bv  = (const float*)d_in[7];
    const float* Wp  = (const float*)d_in[8];
    const float* bp  = (const float*)d_in[9];
    float* out = (float*)d_out;

    cudaFuncSetAttribute(gemm_mma_kernel<0>, cudaFuncAttributeMaxDynamicSharedMemorySize, GSMEM);
    cudaFuncSetAttribute(gemm_mma_kernel<1>, cudaFuncAttributeMaxDynamicSharedMemorySize, GSMEM);
    cudaFuncSetAttribute(gemm_mma_kernel<2>, cudaFuncAttributeMaxDynamicSharedMemorySize, GSMEM);
    cudaFuncSetAttribute(gemm_mma_kernel<3>, cudaFuncAttributeMaxDynamicSharedMemorySize, GSMEM);
    cudaFuncSetAttribute(attn_mma_kernel, cudaFuncAttributeMaxDynamicSharedMemorySize, ASMEM);

    const dim3 gg(HIDq / 128, Mq / 128);   // 8 x 64

    convert_x_kernel<<<(Mq * HIDq) / (256 * 8), 256>>>(x);
    convw_all_kernel<<<dim3(32, 32, 4), 256>>>(Wq, Wk, Wv, Wp);

    gemm_mma_kernel<0><<<gg, 256, GSMEM>>>(bq, nullptr);
    gemm_mma_kernel<1><<<gg, 256, GSMEM>>>(bk, nullptr);
    gemm_mma_kernel<2><<<gg, 256, GSMEM>>>(bv, nullptr);

    attn_mma_kernel<<<dim3(Sq / 128, Bq * NHq), 256, ASMEM>>>(msk);

    gemm_mma_kernel<3><<<gg, 256, GSMEM>>>(bp, out);
}

// round 9
// speedup vs baseline: 6.3461x; 1.4338x over previous
#include <cuda_runtime.h>
#include <cuda_fp16.h>
#include <cstdint>

#define Bq   8
#define Sq   1024
#define HIDq 1024
#define NHq  16
#define HDq  64
#define Mq   (Bq * Sq)   // 8192

// Scratch (device globals: allocation-free per harness rules)
__device__ __half g_xh[(size_t)Mq * HIDq];     // A operand fp16 [M,K] (x, later ctx)
__device__ __half g_wt4[(size_t)4 * HIDq * HIDq];  // W^T fp16 [4][N,K] (q,k,v,p)
__device__ __half g_qh[(size_t)Bq * NHq * Sq * HDq];  // [B,NH,S,HD] (pre-scaled)
__device__ __half g_kh[(size_t)Bq * NHq * Sq * HDq];
__device__ __half g_vh[(size_t)Bq * NHq * Sq * HDq];

// ===========================================================================
// PTX helpers (portable tensor ISA: ldmatrix + mma.sync, sm_80+)
// ===========================================================================
__device__ __forceinline__ uint32_t smem_to_u32(const void* p) {
    uint32_t a;
    asm("{ .reg .u64 t; cvta.to.shared.u64 t, %1; cvt.u32.u64 %0, t; }"
        : "=r"(a) : "l"(p));
    return a;
}

#define LDMX4(r, addr) \
    asm volatile("ldmatrix.sync.aligned.m8n8.x4.shared.b16 {%0,%1,%2,%3}, [%4];" \
        : "=r"((r)[0]), "=r"((r)[1]), "=r"((r)[2]), "=r"((r)[3]) : "r"(addr))

#define LDMX2(r, addr) \
    asm volatile("ldmatrix.sync.aligned.m8n8.x2.shared.b16 {%0,%1}, [%2];" \
        : "=r"((r)[0]), "=r"((r)[1]) : "r"(addr))

#define LDMX2T(r, addr) \
    asm volatile("ldmatrix.sync.aligned.m8n8.x2.trans.shared.b16 {%0,%1}, [%2];" \
        : "=r"((r)[0]), "=r"((r)[1]) : "r"(addr))

#define MMA_F16(d, a, b) \
    asm volatile("mma.sync.aligned.m16n8k16.row.col.f32.f16.f16.f32 " \
        "{%0,%1,%2,%3}, {%4,%5,%6,%7}, {%8,%9}, {%0,%1,%2,%3};" \
        : "+f"((d)[0]), "+f"((d)[1]), "+f"((d)[2]), "+f"((d)[3]) \
        : "r"((a)[0]), "r"((a)[1]), "r"((a)[2]), "r"((a)[3]), \
          "r"((b)[0]), "r"((b)[1]))

#define CP_ASYNC16(smem, gmem) \
    asm volatile("cp.async.cg.shared.global [%0], [%1], 16;" \
        :: "r"(smem), "l"(gmem) : "memory")
#define CP_COMMIT()  asm volatile("cp.async.commit_group;" ::: "memory")
#define CP_WAIT(n)   asm volatile("cp.async.wait_group %0;" :: "n"(n) : "memory")

// ===========================================================================
// Conversion: x fp32 -> fp16
// ===========================================================================
__global__ __launch_bounds__(256) void convert_x_kernel(const float* __restrict__ src)
{
    const size_t i = ((size_t)blockIdx.x * 256 + threadIdx.x) * 8;
    float4 v0 = *(const float4*)(src + i);
    float4 v1 = *(const float4*)(src + i + 4);
    __half2 h0 = __floats2half2_rn(v0.x, v0.y);
    __half2 h1 = __floats2half2_rn(v0.z, v0.w);
    __half2 h2 = __floats2half2_rn(v1.x, v1.y);
    __half2 h3 = __floats2half2_rn(v1.z, v1.w);
    *(uint4*)(g_xh + i) = make_uint4(*(uint32_t*)&h0, *(uint32_t*)&h1,
                                     *(uint32_t*)&h2, *(uint32_t*)&h3);
}

// ===========================================================================
// All-weights transpose: g_wt4[z][n][k] = fp16(Wz[k][n]) for z in {q,k,v,p}
// ===========================================================================
__global__ __launch_bounds__(256) void convw_all_kernel(
    const float* __restrict__ W0, const float* __restrict__ W1,
    const float* __restrict__ W2, const float* __restrict__ W3)
{
    __shared__ float tile[32][33];
    const float* W = (blockIdx.z == 0) ? W0 : (blockIdx.z == 1) ? W1
                   : (blockIdx.z == 2) ? W2 : W3;
    __half* dst = g_wt4 + (size_t)blockIdx.z * HIDq * HIDq;
    const int bx = blockIdx.x * 32, by = blockIdx.y * 32;
    const int tx = threadIdx.x & 31, ty = threadIdx.x >> 5;  // 32 x 8
#pragma unroll
    for (int i = 0; i < 4; i++)
        tile[ty + i * 8][tx] = W[(size_t)(by + ty + i * 8) * HIDq + bx + tx];
    __syncthreads();
#pragma unroll
    for (int i = 0; i < 4; i++)
        dst[(size_t)(bx + ty + i * 8) * HIDq + by + tx] =
            __float2half(tile[tx][ty + i * 8]);
}

// ===========================================================================
// fp16 mma.sync GEMM: C = Xh[8192,1024] @ g_wt4[MODE] + bias
// MODE 0: fp16, pre-scaled by rsqrt(HID) -> g_qh   [B,NH,S,HD]
// MODE 1: fp16                           -> g_kh
// MODE 2: fp16                           -> g_vh
// MODE 3: fp32 row-major                 -> d_out
// ===========================================================================
#define KCH     32
#define TILEB   (128 * 40 * 2)          // 10240 B per tile (row stride 80 B)
#define GSMEM   (4 * TILEB)             // 40960 B (2 bufs x {A, B})

template <int MODE>
__global__ __launch_bounds__(256, 2) void gemm_mma_kernel(
    const float* __restrict__ bias, float* __restrict__ Cout)
{
    extern __shared__ char sm[];
    const uint32_t sb = smem_to_u32(sm);
    const __half* Wt = g_wt4 + (size_t)MODE * HIDq * HIDq;

    const int tid = threadIdx.x, lane = tid & 31, wid = tid >> 5;
    const int wm = wid >> 2, wn = wid & 3;             // 2 x 4 warp grid
    const int bm = blockIdx.y * 128, bn = blockIdx.x * 128;

    float acc[4][4][4];
#pragma unroll
    for (int mi = 0; mi < 4; mi++)
#pragma unroll
        for (int ni = 0; ni < 4; ni++)
#pragma unroll
            for (int r = 0; r < 4; r++) acc[mi][ni][r] = 0.f;

    const int g0 = tid, g1 = tid + 256;
    const int r0g = g0 >> 2, s0 = g0 & 3;
    const int r1g = g1 >> 2, s1 = g1 & 3;

    auto issue = [&](int c) {
        const int p = c & 1;
        const uint32_t base = sb + (uint32_t)p * 2 * TILEB;
        const int k0 = c * KCH;
        const uint32_t so0 = (uint32_t)r0g * 80 + (uint32_t)s0 * 16;
        const uint32_t so1 = (uint32_t)r1g * 80 + (uint32_t)s1 * 16;
        CP_ASYNC16(base + so0,         g_xh + (size_t)(bm + r0g) * HIDq + k0 + s0 * 8);
        CP_ASYNC16(base + so1,         g_xh + (size_t)(bm + r1g) * HIDq + k0 + s1 * 8);
        CP_ASYNC16(base + TILEB + so0, Wt   + (size_t)(bn + r0g) * HIDq + k0 + s0 * 8);
        CP_ASYNC16(base + TILEB + so1, Wt   + (size_t)(bn + r1g) * HIDq + k0 + s1 * 8);
        CP_COMMIT();
    };

    issue(0);

    for (int c = 0; c < HIDq / KCH; c++) {
        if (c + 1 < HIDq / KCH) { issue(c + 1); CP_WAIT(1); }
        else                    { CP_WAIT(0); }
        __syncthreads();

        const uint32_t base = sb + (uint32_t)(c & 1) * 2 * TILEB;

#pragma unroll
        for (int kk = 0; kk < KCH; kk += 16) {
            uint32_t bh[4][2];
#pragma unroll
            for (int ni = 0; ni < 4; ni++) {
                const uint32_t baddr = base + TILEB
                    + (uint32_t)(wn * 32 + ni * 8 + (lane & 7)) * 80
                    + (uint32_t)(kk + ((lane >> 3) & 1) * 8) * 2;
                LDMX2(bh[ni], baddr);
            }
#pragma unroll
            for (int mi = 0; mi < 4; mi++) {
                const uint32_t aaddr = base
                    + (uint32_t)(wm * 64 + mi * 16 + (lane & 15)) * 80
                    + (uint32_t)(kk + (lane >> 4) * 8) * 2;
                uint32_t ah[4];
                LDMX4(ah, aaddr);
#pragma unroll
                for (int ni = 0; ni < 4; ni++)
                    MMA_F16(acc[mi][ni], ah, bh[ni]);
            }
        }
        __syncthreads();
    }

    const int rbase = bm + wm * 64 + (lane >> 2);
    const int cbase = bn + wn * 32 + (lane & 3) * 2;
#pragma unroll
    for (int mi = 0; mi < 4; mi++) {
#pragma unroll
        for (int ni = 0; ni < 4; ni++) {
            const int col = cbase + ni * 8;
            const float2 b2 = *(const float2*)(bias + col);
#pragma unroll
            for (int half = 0; half < 2; half++) {
                const int row = rbase + mi * 16 + half * 8;
                float ox = acc[mi][ni][half * 2 + 0] + b2.x;
                float oy = acc[mi][ni][half * 2 + 1] + b2.y;
                if (MODE == 3) {
                    *(float2*)(Cout + (size_t)row * HIDq + col) = make_float2(ox, oy);
                } else {
                    const int b = row >> 10, s = row & 1023;
                    const int h = col >> 6,  d = col & 63;
                    const size_t off = (((size_t)(b * NHq + h)) * Sq + s) * HDq + d;
                    if (MODE == 0) { ox *= 0.03125f; oy *= 0.03125f; }
                    __half2 h2 = __floats2half2_rn(ox, oy);
                    __half* dst = (MODE == 0) ? g_qh : (MODE == 1) ? g_kh : g_vh;
                    *(uint32_t*)(dst + off) = *(uint32_t*)&h2;
                }
            }
        }
    }
}

// ===========================================================================
// fp16 flash attention: per (b,h), 128-query tile, 64-key stages (2-stage).
// 256 threads = 8 warps, warp owns 16 query rows.
// Scores: Q*K (1 MMA); PV: P*V (1 MMA). smem 55 KB.
// ctx -> fp16 into g_xh [B*S, HID].
// ===========================================================================
#define QTILE  18432                    // 128 rows x 144 B
#define KVTILE 9216                     // 64 rows x 144 B
#define KVSTG  (2 * KVTILE)             // Kh, Vh
#define KVOFF  QTILE
#define ASMEM  (KVOFF + 2 * KVSTG)      // 55296
#define NTK    (Sq / 64)                // 16

__global__ __launch_bounds__(256, 2) void attn_mma_kernel(const float* __restrict__ mask)
{
    extern __shared__ char sm[];
    const uint32_t sb = smem_to_u32(sm);

    const int bh = blockIdx.y;
    const int b = bh >> 4, h = bh & 15;
    const int qbase = blockIdx.x * 128;
    const int tid = threadIdx.x, lane = tid & 31, wid = tid >> 5;
    const int wrow = wid * 16;

    const size_t hb = (size_t)bh * Sq * HDq;
    const __half* Qg = g_qh + hb;
    const __half* KVg[2] = {g_kh + hb, g_vh + hb};

    // Q load (joins cp.async group 0 with KV stage 0)
#pragma unroll
    for (int t = 0; t < 4; t++) {
        const int id = t * 256 + tid;
        const int row = id >> 3, seg = id & 7;
        CP_ASYNC16(sb + (uint32_t)row * 144 + seg * 16,
                   Qg + (size_t)(qbase + row) * HDq + seg * 8);
    }

    auto issue_kv = [&](int kt) {
        const uint32_t base = sb + KVOFF + (uint32_t)(kt & 1) * KVSTG;
#pragma unroll
        for (int t = 0; t < 4; t++) {
            const int which = t >> 1;           // 0=Kh, 1=Vh
            const int id = (t & 1) * 256 + tid;
            const int row = id >> 3, seg = id & 7;
            CP_ASYNC16(base + (uint32_t)which * KVTILE + (uint32_t)row * 144 + seg * 16,
                       KVg[which] + (size_t)(kt * 64 + row) * HDq + seg * 8);
        }
        CP_COMMIT();
    };

    issue_kv(0);

    float m_st[2] = {-1e30f, -1e30f};
    float l_st[2] = {0.f, 0.f};
    float ctx[8][4];
#pragma unroll
    for (int n = 0; n < 8; n++)
#pragma unroll
        for (int r = 0; r < 4; r++) ctx[n][r] = 0.f;

    const int r0 = qbase + wrow + (lane >> 2);

    for (int kt = 0; kt < NTK; kt++) {
        if (kt + 1 < NTK) { issue_kv(kt + 1); CP_WAIT(1); }
        else              { CP_WAIT(0); }
        __syncthreads();

        const uint32_t kvb = sb + KVOFF + (uint32_t)(kt & 1) * KVSTG;

        // ---- scores S = Q K^T ----
        float accs[8][4];
#pragma unroll
        for (int n = 0; n < 8; n++)
#pragma unroll
            for (int r = 0; r < 4; r++) accs[n][r] = 0.f;

#pragma unroll
        for (int k0 = 0; k0 < 64; k0 += 16) {
            uint32_t ah[4];
            const uint32_t aaddr = sb + (uint32_t)(wrow + (lane & 15)) * 144
                                 + (uint32_t)(k0 + (lane >> 4) * 8) * 2;
            LDMX4(ah, aaddr);
#pragma unroll
            for (int n = 0; n < 8; n++) {
                const uint32_t baddr = kvb + (uint32_t)(n * 8 + (lane & 7)) * 144
                                     + (uint32_t)(k0 + ((lane >> 3) & 1) * 8) * 2;
                uint32_t kb[2];
                LDMX2(kb, baddr);
                MMA_F16(accs[n], ah, kb);
            }
        }

        // ---- mask (scale already folded into Q) ----
        const float* mrow0 = mask + ((size_t)b * Sq + r0) * Sq + kt * 64 + (lane & 3) * 2;
        const float* mrow1 = mrow0 + 8 * Sq;
#pragma unroll
        for (int n = 0; n < 8; n++) {
            const float2 m0 = *(const float2*)(mrow0 + n * 8);
            const float2 m1 = *(const float2*)(mrow1 + n * 8);
            accs[n][0] = fmaf(m0.x, -1e9f, accs[n][0]);
            accs[n][1] = fmaf(m0.y, -1e9f, accs[n][1]);
            accs[n][2] = fmaf(m1.x, -1e9f, accs[n][2]);
            accs[n][3] = fmaf(m1.y, -1e9f, accs[n][3]);
        }

        // ---- online softmax (rows r0, r0+8) ----
        float mx0 = -1e30f, mx1 = -1e30f;
#pragma unroll
        for (int n = 0; n < 8; n++) {
            mx0 = fmaxf(mx0, fmaxf(accs[n][0], accs[n][1]));
            mx1 = fmaxf(mx1, fmaxf(accs[n][2], accs[n][3]));
        }
        mx0 = fmaxf(mx0, __shfl_xor_sync(0xffffffffu, mx0, 1));
        mx0 = fmaxf(mx0, __shfl_xor_sync(0xffffffffu, mx0, 2));
        mx1 = fmaxf(mx1, __shfl_xor_sync(0xffffffffu, mx1, 1));
        mx1 = fmaxf(mx1, __shfl_xor_sync(0xffffffffu, mx1, 2));

        const float mn0 = fmaxf(m_st[0], mx0);
        const float mn1 = fmaxf(m_st[1], mx1);
        const float al0 = __expf(m_st[0] - mn0);
        const float al1 = __expf(m_st[1] - mn1);
        m_st[0] = mn0; m_st[1] = mn1;

        float sum0 = 0.f, sum1 = 0.f;
#pragma unroll
        for (int n = 0; n < 8; n++) {
            accs[n][0] = __expf(accs[n][0] - mn0);
            accs[n][1] = __expf(accs[n][1] - mn0);
            accs[n][2] = __expf(accs[n][2] - mn1);
            accs[n][3] = __expf(accs[n][3] - mn1);
            sum0 += accs[n][0] + accs[n][1];
            sum1 += accs[n][2] + accs[n][3];
        }
        sum0 += __shfl_xor_sync(0xffffffffu, sum0, 1);
        sum0 += __shfl_xor_sync(0xffffffffu, sum0, 2);
        sum1 += __shfl_xor_sync(0xffffffffu, sum1, 1);
        sum1 += __shfl_xor_sync(0xffffffffu, sum1, 2);
        l_st[0] = l_st[0] * al0 + sum0;
        l_st[1] = l_st[1] * al1 + sum1;

#pragma unroll
        for (int n = 0; n < 8; n++) {
            ctx[n][0] *= al0; ctx[n][1] *= al0;
            ctx[n][2] *= al1; ctx[n][3] *= al1;
        }

        // ---- PV: ctx += P_fp16 V ----
        const uint32_t vbase = kvb + KVTILE;
#pragma unroll
        for (int kk2 = 0; kk2 < 4; kk2++) {
            uint32_t pf[4];
            __half2 p0 = __floats2half2_rn(accs[2 * kk2][0],     accs[2 * kk2][1]);
            __half2 p1 = __floats2half2_rn(accs[2 * kk2][2],     accs[2 * kk2][3]);
            __half2 p2 = __floats2half2_rn(accs[2 * kk2 + 1][0], accs[2 * kk2 + 1][1]);
            __half2 p3 = __floats2half2_rn(accs[2 * kk2 + 1][2], accs[2 * kk2 + 1][3]);
            pf[0] = *(uint32_t*)&p0; pf[1] = *(uint32_t*)&p1;
            pf[2] = *(uint32_t*)&p2; pf[3] = *(uint32_t*)&p3;
#pragma unroll
            for (int n = 0; n < 8; n++) {
                const uint32_t vaddr = vbase + (uint32_t)(kk2 * 16 + (lane & 15)) * 144
                                     + (uint32_t)n * 16;
                uint32_t vh[2];
                LDMX2T(vh, vaddr);
                MMA_F16(ctx[n], pf, vh);
            }
        }
        __syncthreads();
    }

    // ---- epilogue: ctx / l -> fp16 into g_xh [B*S, HID] ----
    const float inv0 = 1.0f / l_st[0];
    const float inv1 = 1.0f / l_st[1];
    const int cb = h * HDq + (lane & 3) * 2;
#pragma unroll
    for (int n = 0; n < 8; n++) {
        const int col = cb + n * 8;
        const size_t off0 = ((size_t)(b * Sq + r0)) * HIDq + col;
        const size_t off1 = ((size_t)(b * Sq + r0 + 8)) * HIDq + col;
        __half2 h0 = __floats2half2_rn(ctx[n][0] * inv0, ctx[n][1] * inv0);
        __half2 h1 = __floats2half2_rn(ctx[n][2] * inv1, ctx[n][3] * inv1);
        *(uint32_t*)(g_xh + off0) = *(uint32_t*)&h0;
        *(uint32_t*)(g_xh + off1) = *(uint32_t*)&h1;
    }
}

// ---------------------------------------------------------------------------
extern "C" void kernel_launch(void* const* d_in, const int* in_sizes, int n_in,
                              void* d_out, int out_size)
{
    (void)in_sizes; (void)n_in; (void)out_size;
    const float* x   = (const float*)d_in[0];
    const float* msk = (const float*)d_in[1];
    const float* Wq  = (const float*)d_in[2];
    const float* bq  = (const float*)d_in[3];
    const float* Wk  = (const float*)d_in[4];
    const float* bk  = (const float*)d_in[5];
    const float* Wv  = (const float*)d_in[6];
    const float* bv  = (const float*)d_in[7];
    const float* Wp  = (const float*)d_in[8];
    const float* bp  = (const float*)d_in[9];
    float* out = (float*)d_out;

    cudaFuncSetAttribute(gemm_mma_kernel<0>, cudaFuncAttributeMaxDynamicSharedMemorySize, GSMEM);
    cudaFuncSetAttribute(gemm_mma_kernel<1>, cudaFuncAttributeMaxDynamicSharedMemorySize, GSMEM);
    cudaFuncSetAttribute(gemm_mma_kernel<2>, cudaFuncAttributeMaxDynamicSharedMemorySize, GSMEM);
    cudaFuncSetAttribute(gemm_mma_kernel<3>, cudaFuncAttributeMaxDynamicSharedMemorySize, GSMEM);
    cudaFuncSetAttribute(attn_mma_kernel, cudaFuncAttributeMaxDynamicSharedMemorySize, ASMEM);

    const dim3 gg(HIDq / 128, Mq / 128);   // 8 x 64

    convert_x_kernel<<<(Mq * HIDq) / (256 * 8), 256>>>(x);
    convw_all_kernel<<<dim3(32, 32, 4), 256>>>(Wq, Wk, Wv, Wp);

    gemm_mma_kernel<0><<<gg, 256, GSMEM>>>(bq, nullptr);
    gemm_mma_kernel<1><<<gg, 256, GSMEM>>>(bk, nullptr);
    gemm_mma_kernel<2><<<gg, 256, GSMEM>>>(bv, nullptr);

    attn_mma_kernel<<<dim3(Sq / 128, Bq * NHq), 256, ASMEM>>>(msk);

    gemm_mma_kernel<3><<<gg, 256, GSMEM>>>(bp, out);
}

// round 10
// speedup vs baseline: 7.2384x; 1.1406x over previous
#include <cuda_runtime.h>
#include <cuda_fp16.h>
#include <cstdint>

#define Bq   8
#define Sq   1024
#define HIDq 1024
#define NHq  16
#define HDq  64
#define Mq   (Bq * Sq)   // 8192

// Scratch (device globals: allocation-free per harness rules)
__device__ __half g_xh[(size_t)Mq * HIDq];     // A operand fp16 [M,K] (x, later ctx)
__device__ __half g_wt4[(size_t)4 * HIDq * HIDq];  // W^T fp16 [4][N,K] (q,k,v,p)
__device__ __half g_qh[(size_t)Bq * NHq * Sq * HDq];  // [B,NH,S,HD] (pre-scaled)
__device__ __half g_kh[(size_t)Bq * NHq * Sq * HDq];
__device__ __half g_vh[(size_t)Bq * NHq * Sq * HDq];

// ===========================================================================
// PTX helpers (portable tensor ISA: ldmatrix + mma.sync, sm_80+)
// ===========================================================================
__device__ __forceinline__ uint32_t smem_to_u32(const void* p) {
    uint32_t a;
    asm("{ .reg .u64 t; cvta.to.shared.u64 t, %1; cvt.u32.u64 %0, t; }"
        : "=r"(a) : "l"(p));
    return a;
}

#define LDMX4(r, addr) \
    asm volatile("ldmatrix.sync.aligned.m8n8.x4.shared.b16 {%0,%1,%2,%3}, [%4];" \
        : "=r"((r)[0]), "=r"((r)[1]), "=r"((r)[2]), "=r"((r)[3]) : "r"(addr))

#define LDMX2(r, addr) \
    asm volatile("ldmatrix.sync.aligned.m8n8.x2.shared.b16 {%0,%1}, [%2];" \
        : "=r"((r)[0]), "=r"((r)[1]) : "r"(addr))

#define LDMX2T(r, addr) \
    asm volatile("ldmatrix.sync.aligned.m8n8.x2.trans.shared.b16 {%0,%1}, [%2];" \
        : "=r"((r)[0]), "=r"((r)[1]) : "r"(addr))

#define MMA_F16(d, a, b) \
    asm volatile("mma.sync.aligned.m16n8k16.row.col.f32.f16.f16.f32 " \
        "{%0,%1,%2,%3}, {%4,%5,%6,%7}, {%8,%9}, {%0,%1,%2,%3};" \
        : "+f"((d)[0]), "+f"((d)[1]), "+f"((d)[2]), "+f"((d)[3]) \
        : "r"((a)[0]), "r"((a)[1]), "r"((a)[2]), "r"((a)[3]), \
          "r"((b)[0]), "r"((b)[1]))

#define CP_ASYNC16(smem, gmem) \
    asm volatile("cp.async.cg.shared.global [%0], [%1], 16;" \
        :: "r"(smem), "l"(gmem) : "memory")
#define CP_COMMIT()  asm volatile("cp.async.commit_group;" ::: "memory")
#define CP_WAIT(n)   asm volatile("cp.async.wait_group %0;" :: "n"(n) : "memory")

// ===========================================================================
// Conversion: x fp32 -> fp16
// ===========================================================================
__global__ __launch_bounds__(256) void convert_x_kernel(const float* __restrict__ src)
{
    const size_t i = ((size_t)blockIdx.x * 256 + threadIdx.x) * 8;
    float4 v0 = *(const float4*)(src + i);
    float4 v1 = *(const float4*)(src + i + 4);
    __half2 h0 = __floats2half2_rn(v0.x, v0.y);
    __half2 h1 = __floats2half2_rn(v0.z, v0.w);
    __half2 h2 = __floats2half2_rn(v1.x, v1.y);
    __half2 h3 = __floats2half2_rn(v1.z, v1.w);
    *(uint4*)(g_xh + i) = make_uint4(*(uint32_t*)&h0, *(uint32_t*)&h1,
                                     *(uint32_t*)&h2, *(uint32_t*)&h3);
}

// ===========================================================================
// All-weights transpose: g_wt4[z][n][k] = fp16(Wz[k][n]) for z in {q,k,v,p}
// ===========================================================================
__global__ __launch_bounds__(256) void convw_all_kernel(
    const float* __restrict__ W0, const float* __restrict__ W1,
    const float* __restrict__ W2, const float* __restrict__ W3)
{
    __shared__ float tile[32][33];
    const float* W = (blockIdx.z == 0) ? W0 : (blockIdx.z == 1) ? W1
                   : (blockIdx.z == 2) ? W2 : W3;
    __half* dst = g_wt4 + (size_t)blockIdx.z * HIDq * HIDq;
    const int bx = blockIdx.x * 32, by = blockIdx.y * 32;
    const int tx = threadIdx.x & 31, ty = threadIdx.x >> 5;  // 32 x 8
#pragma unroll
    for (int i = 0; i < 4; i++)
        tile[ty + i * 8][tx] = W[(size_t)(by + ty + i * 8) * HIDq + bx + tx];
    __syncthreads();
#pragma unroll
    for (int i = 0; i < 4; i++)
        dst[(size_t)(bx + ty + i * 8) * HIDq + by + tx] =
            __float2half(tile[tx][ty + i * 8]);
}

// ===========================================================================
// fp16 mma.sync GEMM core. KCH=64 (16 chunks), 2-stage cp.async pipeline.
// CTA 128x128, 8 warps (2m x 4n). Row stride 144 B (conflict-free).
// ===========================================================================
#define KCH    64
#define GTILE  18432                    // 128 rows x 144 B
#define GSTG   (2 * GTILE)              // A + B per stage
#define GSMEM  (2 * GSTG)               // 73728 B, 2 stages

// QKV merged GEMM: z = blockIdx.z selects weight slot, bias, destination.
__global__ __launch_bounds__(256, 2) void gemm_qkv_kernel(
    const float* __restrict__ b0, const float* __restrict__ b1,
    const float* __restrict__ b2)
{
    extern __shared__ char sm[];
    const uint32_t sb = smem_to_u32(sm);
    const int z = blockIdx.z;
    const __half* Wt = g_wt4 + (size_t)z * HIDq * HIDq;
    const float* bias = (z == 0) ? b0 : (z == 1) ? b1 : b2;
    __half* dst = (z == 0) ? g_qh : (z == 1) ? g_kh : g_vh;

    const int tid = threadIdx.x, lane = tid & 31, wid = tid >> 5;
    const int wm = wid >> 2, wn = wid & 3;
    const int bm = blockIdx.y * 128, bn = blockIdx.x * 128;

    float acc[4][4][4];
#pragma unroll
    for (int mi = 0; mi < 4; mi++)
#pragma unroll
        for (int ni = 0; ni < 4; ni++)
#pragma unroll
            for (int r = 0; r < 4; r++) acc[mi][ni][r] = 0.f;

    auto issue = [&](int c) {
        const uint32_t base = sb + (uint32_t)(c & 1) * GSTG;
        const int k0 = c * KCH;
#pragma unroll
        for (int t = 0; t < 4; t++) {
            const int id = t * 256 + tid;
            const int row = id >> 3, seg = id & 7;
            const uint32_t so = (uint32_t)row * 144 + seg * 16;
            CP_ASYNC16(base + so,         g_xh + (size_t)(bm + row) * HIDq + k0 + seg * 8);
            CP_ASYNC16(base + GTILE + so, Wt   + (size_t)(bn + row) * HIDq + k0 + seg * 8);
        }
        CP_COMMIT();
    };

    issue(0);

    for (int c = 0; c < HIDq / KCH; c++) {
        if (c + 1 < HIDq / KCH) { issue(c + 1); CP_WAIT(1); }
        else                    { CP_WAIT(0); }
        __syncthreads();

        const uint32_t base = sb + (uint32_t)(c & 1) * GSTG;

#pragma unroll
        for (int kk = 0; kk < KCH; kk += 16) {
            uint32_t bh[4][2];
#pragma unroll
            for (int ni = 0; ni < 4; ni++) {
                const uint32_t baddr = base + GTILE
                    + (uint32_t)(wn * 32 + ni * 8 + (lane & 7)) * 144
                    + (uint32_t)(kk + ((lane >> 3) & 1) * 8) * 2;
                LDMX2(bh[ni], baddr);
            }
#pragma unroll
            for (int mi = 0; mi < 4; mi++) {
                const uint32_t aaddr = base
                    + (uint32_t)(wm * 64 + mi * 16 + (lane & 15)) * 144
                    + (uint32_t)(kk + (lane >> 4) * 8) * 2;
                uint32_t ah[4];
                LDMX4(ah, aaddr);
#pragma unroll
                for (int ni = 0; ni < 4; ni++)
                    MMA_F16(acc[mi][ni], ah, bh[ni]);
            }
        }
        __syncthreads();
    }

    const int rbase = bm + wm * 64 + (lane >> 2);
    const int cbase = bn + wn * 32 + (lane & 3) * 2;
    const float qs = (z == 0) ? 0.03125f : 1.0f;
#pragma unroll
    for (int mi = 0; mi < 4; mi++) {
#pragma unroll
        for (int ni = 0; ni < 4; ni++) {
            const int col = cbase + ni * 8;
            const float2 b2v = *(const float2*)(bias + col);
#pragma unroll
            for (int half = 0; half < 2; half++) {
                const int row = rbase + mi * 16 + half * 8;
                const float ox = (acc[mi][ni][half * 2 + 0] + b2v.x) * qs;
                const float oy = (acc[mi][ni][half * 2 + 1] + b2v.y) * qs;
                const int b = row >> 10, s = row & 1023;
                const int h = col >> 6,  d = col & 63;
                const size_t off = (((size_t)(b * NHq + h)) * Sq + s) * HDq + d;
                __half2 h2 = __floats2half2_rn(ox, oy);
                *(uint32_t*)(dst + off) = *(uint32_t*)&h2;
            }
        }
    }
}

// Output projection: A = g_xh (ctx), W slot 3, fp32 row-major to d_out.
__global__ __launch_bounds__(256, 2) void gemm_out_kernel(
    const float* __restrict__ bias, float* __restrict__ Cout)
{
    extern __shared__ char sm[];
    const uint32_t sb = smem_to_u32(sm);
    const __half* Wt = g_wt4 + (size_t)3 * HIDq * HIDq;

    const int tid = threadIdx.x, lane = tid & 31, wid = tid >> 5;
    const int wm = wid >> 2, wn = wid & 3;
    const int bm = blockIdx.y * 128, bn = blockIdx.x * 128;

    float acc[4][4][4];
#pragma unroll
    for (int mi = 0; mi < 4; mi++)
#pragma unroll
        for (int ni = 0; ni < 4; ni++)
#pragma unroll
            for (int r = 0; r < 4; r++) acc[mi][ni][r] = 0.f;

    auto issue = [&](int c) {
        const uint32_t base = sb + (uint32_t)(c & 1) * GSTG;
        const int k0 = c * KCH;
#pragma unroll
        for (int t = 0; t < 4; t++) {
            const int id = t * 256 + tid;
            const int row = id >> 3, seg = id & 7;
            const uint32_t so = (uint32_t)row * 144 + seg * 16;
            CP_ASYNC16(base + so,         g_xh + (size_t)(bm + row) * HIDq + k0 + seg * 8);
            CP_ASYNC16(base + GTILE + so, Wt   + (size_t)(bn + row) * HIDq + k0 + seg * 8);
        }
        CP_COMMIT();
    };

    issue(0);

    for (int c = 0; c < HIDq / KCH; c++) {
        if (c + 1 < HIDq / KCH) { issue(c + 1); CP_WAIT(1); }
        else                    { CP_WAIT(0); }
        __syncthreads();

        const uint32_t base = sb + (uint32_t)(c & 1) * GSTG;

#pragma unroll
        for (int kk = 0; kk < KCH; kk += 16) {
            uint32_t bh[4][2];
#pragma unroll
            for (int ni = 0; ni < 4; ni++) {
                const uint32_t baddr = base + GTILE
                    + (uint32_t)(wn * 32 + ni * 8 + (lane & 7)) * 144
                    + (uint32_t)(kk + ((lane >> 3) & 1) * 8) * 2;
                LDMX2(bh[ni], baddr);
            }
#pragma unroll
            for (int mi = 0; mi < 4; mi++) {
                const uint32_t aaddr = base
                    + (uint32_t)(wm * 64 + mi * 16 + (lane & 15)) * 144
                    + (uint32_t)(kk + (lane >> 4) * 8) * 2;
                uint32_t ah[4];
                LDMX4(ah, aaddr);
#pragma unroll
                for (int ni = 0; ni < 4; ni++)
                    MMA_F16(acc[mi][ni], ah, bh[ni]);
            }
        }
        __syncthreads();
    }

    const int rbase = bm + wm * 64 + (lane >> 2);
    const int cbase = bn + wn * 32 + (lane & 3) * 2;
#pragma unroll
    for (int mi = 0; mi < 4; mi++) {
#pragma unroll
        for (int ni = 0; ni < 4; ni++) {
            const int col = cbase + ni * 8;
            const float2 b2v = *(const float2*)(bias + col);
#pragma unroll
            for (int half = 0; half < 2; half++) {
                const int row = rbase + mi * 16 + half * 8;
                *(float2*)(Cout + (size_t)row * HIDq + col) =
                    make_float2(acc[mi][ni][half * 2 + 0] + b2v.x,
                                acc[mi][ni][half * 2 + 1] + b2v.y);
            }
        }
    }
}

// ===========================================================================
// fp16 flash attention: per (b,h), 128-query tile, 64-key stages (2-stage).
// Scores: Q*K (1 MMA); PV: P*V (1 MMA). smem 55 KB, 2 CTAs/SM.
// ctx -> fp16 into g_xh [B*S, HID].
// ===========================================================================
#define QTILE  18432                    // 128 rows x 144 B
#define KVTILE 9216                     // 64 rows x 144 B
#define KVSTG  (2 * KVTILE)             // Kh, Vh
#define KVOFF  QTILE
#define ASMEM  (KVOFF + 2 * KVSTG)      // 55296
#define NTK    (Sq / 64)                // 16

__global__ __launch_bounds__(256, 2) void attn_mma_kernel(const float* __restrict__ mask)
{
    extern __shared__ char sm[];
    const uint32_t sb = smem_to_u32(sm);

    const int bh = blockIdx.y;
    const int b = bh >> 4, h = bh & 15;
    const int qbase = blockIdx.x * 128;
    const int tid = threadIdx.x, lane = tid & 31, wid = tid >> 5;
    const int wrow = wid * 16;

    const size_t hb = (size_t)bh * Sq * HDq;
    const __half* Qg = g_qh + hb;
    const __half* KVg[2] = {g_kh + hb, g_vh + hb};

#pragma unroll
    for (int t = 0; t < 4; t++) {
        const int id = t * 256 + tid;
        const int row = id >> 3, seg = id & 7;
        CP_ASYNC16(sb + (uint32_t)row * 144 + seg * 16,
                   Qg + (size_t)(qbase + row) * HDq + seg * 8);
    }

    auto issue_kv = [&](int kt) {
        const uint32_t base = sb + KVOFF + (uint32_t)(kt & 1) * KVSTG;
#pragma unroll
        for (int t = 0; t < 4; t++) {
            const int which = t >> 1;
            const int id = (t & 1) * 256 + tid;
            const int row = id >> 3, seg = id & 7;
            CP_ASYNC16(base + (uint32_t)which * KVTILE + (uint32_t)row * 144 + seg * 16,
                       KVg[which] + (size_t)(kt * 64 + row) * HDq + seg * 8);
        }
        CP_COMMIT();
    };

    issue_kv(0);

    float m_st[2] = {-1e30f, -1e30f};
    float l_st[2] = {0.f, 0.f};
    float ctx[8][4];
#pragma unroll
    for (int n = 0; n < 8; n++)
#pragma unroll
        for (int r = 0; r < 4; r++) ctx[n][r] = 0.f;

    const int r0 = qbase + wrow + (lane >> 2);

    for (int kt = 0; kt < NTK; kt++) {
        if (kt + 1 < NTK) { issue_kv(kt + 1); CP_WAIT(1); }
        else              { CP_WAIT(0); }
        __syncthreads();

        const uint32_t kvb = sb + KVOFF + (uint32_t)(kt & 1) * KVSTG;

        float accs[8][4];
#pragma unroll
        for (int n = 0; n < 8; n++)
#pragma unroll
            for (int r = 0; r < 4; r++) accs[n][r] = 0.f;

#pragma unroll
        for (int k0 = 0; k0 < 64; k0 += 16) {
            uint32_t ah[4];
            const uint32_t aaddr = sb + (uint32_t)(wrow + (lane & 15)) * 144
                                 + (uint32_t)(k0 + (lane >> 4) * 8) * 2;
            LDMX4(ah, aaddr);
#pragma unroll
            for (int n = 0; n < 8; n++) {
                const uint32_t baddr = kvb + (uint32_t)(n * 8 + (lane & 7)) * 144
                                     + (uint32_t)(k0 + ((lane >> 3) & 1) * 8) * 2;
                uint32_t kb[2];
                LDMX2(kb, baddr);
                MMA_F16(accs[n], ah, kb);
            }
        }

        const float* mrow0 = mask + ((size_t)b * Sq + r0) * Sq + kt * 64 + (lane & 3) * 2;
        const float* mrow1 = mrow0 + 8 * Sq;
#pragma unroll
        for (int n = 0; n < 8; n++) {
            const float2 m0 = *(const float2*)(mrow0 + n * 8);
            const float2 m1 = *(const float2*)(mrow1 + n * 8);
            accs[n][0] = fmaf(m0.x, -1e9f, accs[n][0]);
            accs[n][1] = fmaf(m0.y, -1e9f, accs[n][1]);
            accs[n][2] = fmaf(m1.x, -1e9f, accs[n][2]);
            accs[n][3] = fmaf(m1.y, -1e9f, accs[n][3]);
        }

        float mx0 = -1e30f, mx1 = -1e30f;
#pragma unroll
        for (int n = 0; n < 8; n++) {
            mx0 = fmaxf(mx0, fmaxf(accs[n][0], accs[n][1]));
            mx1 = fmaxf(mx1, fmaxf(accs[n][2], accs[n][3]));
        }
        mx0 = fmaxf(mx0, __shfl_xor_sync(0xffffffffu, mx0, 1));
        mx0 = fmaxf(mx0, __shfl_xor_sync(0xffffffffu, mx0, 2));
        mx1 = fmaxf(mx1, __shfl_xor_sync(0xffffffffu, mx1, 1));
        mx1 = fmaxf(mx1, __shfl_xor_sync(0xffffffffu, mx1, 2));

        const float mn0 = fmaxf(m_st[0], mx0);
        const float mn1 = fmaxf(m_st[1], mx1);
        const float al0 = __expf(m_st[0] - mn0);
        const float al1 = __expf(m_st[1] - mn1);
        m_st[0] = mn0; m_st[1] = mn1;

        float sum0 = 0.f, sum1 = 0.f;
#pragma unroll
        for (int n = 0; n < 8; n++) {
            accs[n][0] = __expf(accs[n][0] - mn0);
            accs[n][1] = __expf(accs[n][1] - mn0);
            accs[n][2] = __expf(accs[n][2] - mn1);
            accs[n][3] = __expf(accs[n][3] - mn1);
            sum0 += accs[n][0] + accs[n][1];
            sum1 += accs[n][2] + accs[n][3];
        }
        sum0 += __shfl_xor_sync(0xffffffffu, sum0, 1);
        sum0 += __shfl_xor_sync(0xffffffffu, sum0, 2);
        sum1 += __shfl_xor_sync(0xffffffffu, sum1, 1);
        sum1 += __shfl_xor_sync(0xffffffffu, sum1, 2);
        l_st[0] = l_st[0] * al0 + sum0;
        l_st[1] = l_st[1] * al1 + sum1;

#pragma unroll
        for (int n = 0; n < 8; n++) {
            ctx[n][0] *= al0; ctx[n][1] *= al0;
            ctx[n][2] *= al1; ctx[n][3] *= al1;
        }

        const uint32_t vbase = kvb + KVTILE;
#pragma unroll
        for (int kk2 = 0; kk2 < 4; kk2++) {
            uint32_t pf[4];
            __half2 p0 = __floats2half2_rn(accs[2 * kk2][0],     accs[2 * kk2][1]);
            __half2 p1 = __floats2half2_rn(accs[2 * kk2][2],     accs[2 * kk2][3]);
            __half2 p2 = __floats2half2_rn(accs[2 * kk2 + 1][0], accs[2 * kk2 + 1][1]);
            __half2 p3 = __floats2half2_rn(accs[2 * kk2 + 1][2], accs[2 * kk2 + 1][3]);
            pf[0] = *(uint32_t*)&p0; pf[1] = *(uint32_t*)&p1;
            pf[2] = *(uint32_t*)&p2; pf[3] = *(uint32_t*)&p3;
#pragma unroll
            for (int n = 0; n < 8; n++) {
                const uint32_t vaddr = vbase + (uint32_t)(kk2 * 16 + (lane & 15)) * 144
                                     + (uint32_t)n * 16;
                uint32_t vh[2];
                LDMX2T(vh, vaddr);
                MMA_F16(ctx[n], pf, vh);
            }
        }
        __syncthreads();
    }

    const float inv0 = 1.0f / l_st[0];
    const float inv1 = 1.0f / l_st[1];
    const int cb = h * HDq + (lane & 3) * 2;
#pragma unroll
    for (int n = 0; n < 8; n++) {
        const int col = cb + n * 8;
        const size_t off0 = ((size_t)(b * Sq + r0)) * HIDq + col;
        const size_t off1 = ((size_t)(b * Sq + r0 + 8)) * HIDq + col;
        __half2 h0 = __floats2half2_rn(ctx[n][0] * inv0, ctx[n][1] * inv0);
        __half2 h1 = __floats2half2_rn(ctx[n][2] * inv1, ctx[n][3] * inv1);
        *(uint32_t*)(g_xh + off0) = *(uint32_t*)&h0;
        *(uint32_t*)(g_xh + off1) = *(uint32_t*)&h1;
    }
}

// ---------------------------------------------------------------------------
extern "C" void kernel_launch(void* const* d_in, const int* in_sizes, int n_in,
                              void* d_out, int out_size)
{
    (void)in_sizes; (void)n_in; (void)out_size;
    const float* x   = (const float*)d_in[0];
    const float* msk = (const float*)d_in[1];
    const float* Wq  = (const float*)d_in[2];
    const float* bq  = (const float*)d_in[3];
    const float* Wk  = (const float*)d_in[4];
    const float* bk  = (const float*)d_in[5];
    const float* Wv  = (const float*)d_in[6];
    const float* bv  = (const float*)d_in[7];
    const float* Wp  = (const float*)d_in[8];
    const float* bp  = (const float*)d_in[9];
    float* out = (float*)d_out;

    cudaFuncSetAttribute(gemm_qkv_kernel, cudaFuncAttributeMaxDynamicSharedMemorySize, GSMEM);
    cudaFuncSetAttribute(gemm_out_kernel, cudaFuncAttributeMaxDynamicSharedMemorySize, GSMEM);
    cudaFuncSetAttribute(attn_mma_kernel, cudaFuncAttributeMaxDynamicSharedMemorySize, ASMEM);

    convert_x_kernel<<<(Mq * HIDq) / (256 * 8), 256>>>(x);
    convw_all_kernel<<<dim3(32, 32, 4), 256>>>(Wq, Wk, Wv, Wp);

    gemm_qkv_kernel<<<dim3(HIDq / 128, Mq / 128, 3), 256, GSMEM>>>(bq, bk, bv);

    attn_mma_kernel<<<dim3(Sq / 128, Bq * NHq), 256, ASMEM>>>(msk);

    gemm_out_kernel<<<dim3(HIDq / 128, Mq / 128), 256, GSMEM>>>(bp, out);
}